// round 14
// baseline (speedup 1.0000x reference)
#include <cuda_runtime.h>
#include <cstdint>

// ---------------------------------------------------------------------------
// Problem constants
// ---------------------------------------------------------------------------
#define NP   500000
#define NB   20000
#define NCA  5000
#define NSH  2000
#define NTOT 527000
#define EE   500000
#define E6   (6 * EE)
#define H    64
#define ODIM 32
#define FIN  384

#define BOFF NP
#define COFF (NP + NB)
#define SOFF (NP + NB + NCA)

#define SCAN_NB ((NTOT + 1023) / 1024)

// ---------------------------------------------------------------------------
// Scratch (device globals: allocation-free rule)
// ---------------------------------------------------------------------------
__device__ float g_x0[(size_t)NTOT * H];
__device__ float g_h1[(size_t)NTOT * H];
__device__ float g_deg[NTOT];
__device__ int   g_cnt[NTOT];
__device__ int   g_row[NTOT + 1];
__device__ int   g_fill[NTOT];
__device__ int   g_eidx[E6];
__device__ unsigned long long g_look[SCAN_NB];

// ---------------------------------------------------------------------------
// f32x2 packed-FMA + cp.async helpers
// ---------------------------------------------------------------------------
__device__ __forceinline__ unsigned long long ffma2(unsigned long long a,
                                                    unsigned long long b,
                                                    unsigned long long c) {
    unsigned long long d;
    asm("fma.rn.f32x2 %0, %1, %2, %3;" : "=l"(d) : "l"(a), "l"(b), "l"(c));
    return d;
}
__device__ __forceinline__ unsigned long long bcast2(float v) {
    unsigned long long r;
    unsigned int u = __float_as_uint(v);
    asm("mov.b64 %0, {%1, %2};" : "=l"(r) : "r"(u), "r"(u));
    return r;
}
__device__ __forceinline__ float2 unpack2(unsigned long long v) {
    unsigned int lo, hi;
    asm("mov.b64 {%0, %1}, %2;" : "=r"(lo), "=r"(hi) : "l"(v));
    return make_float2(__uint_as_float(lo), __uint_as_float(hi));
}
__device__ __forceinline__ void cp_async16(unsigned int smem_dst, const void* gsrc) {
    asm volatile("cp.async.cg.shared.global [%0], [%1], 16;\n"
                 :: "r"(smem_dst), "l"(gsrc));
}
#define CP_COMMIT()  asm volatile("cp.async.commit_group;\n" ::: "memory")
#define CP_WAIT(n)   asm volatile("cp.async.wait_group %0;\n" :: "n"(n) : "memory")

// ---------------------------------------------------------------------------
// Launch 0: zero counts + lookback words
// ---------------------------------------------------------------------------
__global__ void zero_kernel() {
    int i = blockIdx.x * 256 + threadIdx.x;
    if (i < NTOT) g_cnt[i] = 0;
    if (i < SCAN_NB) g_look[i] = 0ull;
}

// ---------------------------------------------------------------------------
// Launch 1: in-degree counts. blockIdx.y = relation id (0..5).
// ---------------------------------------------------------------------------
__global__ void cnt_kernel(const int* __restrict__ pbs, const int* __restrict__ pbd,
                           const int* __restrict__ pcs, const int* __restrict__ pcd,
                           const int* __restrict__ pss, const int* __restrict__ psd) {
    int i = blockIdx.x * 256 + threadIdx.x;
    if (i >= EE) return;
    int d;
    switch (blockIdx.y) {
        case 0:  d = pbd[i] + BOFF; break;
        case 1:  d = pbs[i];        break;
        case 2:  d = pcd[i] + COFF; break;
        case 3:  d = pcs[i];        break;
        case 4:  d = psd[i] + SOFF; break;
        default: d = pss[i];        break;
    }
    atomicAdd(&g_cnt[d], 1);
}

// ---------------------------------------------------------------------------
// Launch 2: decoupled-lookback exclusive scan
// ---------------------------------------------------------------------------
__global__ void scan_kernel() {
    __shared__ int sb[1024];
    __shared__ int s_base;
    const int t = threadIdx.x;
    const int bid = blockIdx.x;
    const int i = bid * 1024 + t;

    int c = (i < NTOT) ? g_cnt[i] : 0;
    sb[t] = c;
    __syncthreads();
    for (int off = 1; off < 1024; off <<= 1) {
        int u = (t >= off) ? sb[t - off] : 0;
        __syncthreads();
        sb[t] += u;
        __syncthreads();
    }
    const int incl = sb[t];
    const int aggregate = sb[1023];

    if (t == 0) {
        unsigned long long st = (bid == 0) ? 2ull : 1ull;
        atomicExch(&g_look[bid], (st << 32) | (unsigned int)aggregate);
    }

    if (bid == 0) {
        if (t == 0) s_base = 0;
    } else if (t < 32) {
        int acc = 0;
        int windowEnd = bid - 1;
        while (true) {
            int p = windowEnd - t;
            unsigned long long w = 0;
            if (p >= 0) w = atomicAdd(&g_look[p], 0ull);
            unsigned int st  = (p >= 0) ? (unsigned int)(w >> 32) : 2u;
            int val          = (p >= 0) ? (int)(unsigned int)w : 0;
            unsigned int ready = __ballot_sync(0xffffffffu, st != 0u);
            if (ready != 0xffffffffu) continue;
            unsigned int haveIncl = __ballot_sync(0xffffffffu, st == 2u);
            if (haveIncl) {
                int L = __ffs(haveIncl) - 1;
                int contrib = (t <= L) ? val : 0;
#pragma unroll
                for (int o = 16; o; o >>= 1)
                    contrib += __shfl_xor_sync(0xffffffffu, contrib, o);
                acc += contrib;
                break;
            } else {
                int contrib = val;
#pragma unroll
                for (int o = 16; o; o >>= 1)
                    contrib += __shfl_xor_sync(0xffffffffu, contrib, o);
                acc += contrib;
                windowEnd -= 32;
            }
        }
        if (t == 0) {
            s_base = acc;
            atomicExch(&g_look[bid],
                       (2ull << 32) | (unsigned int)(acc + aggregate));
        }
    }
    __syncthreads();
    const int base = s_base;

    if (i < NTOT) {
        int excl = base + incl - c;
        g_row[i]  = excl;
        g_fill[i] = excl;
        g_deg[i]  = 1.0f / fmaxf((float)c, 1.0f);
    }
    if (i == NTOT - 1) g_row[NTOT] = E6;
}

// ---------------------------------------------------------------------------
// Launch 3 (PROFILED): projection v4 (reverted R9 champion — 1.0 B/FMA
// crossbar balance). g_x0[0:NP] = relu(x_product @ W_proj^T + b_proj)
// 256 threads, 256 rows/block, 8 rows x 8 cols per thread, FFMA2.
// W^T staged once (coalesced+padded), X via cp.async double buffer.
// ---------------------------------------------------------------------------
#define PROJ_BR 256
#define PROJ_KT 16
#define PROJ_XS 20
#define WT_STR  68
#define PROJ_SMEM ((FIN * WT_STR + 2 * PROJ_BR * PROJ_XS) * 4)   // 145408 B

__global__ void __launch_bounds__(256, 1)
proj_kernel(const float* __restrict__ X,
            const float* __restrict__ W,
            const float* __restrict__ b) {
    extern __shared__ float sm[];
    float* WT = sm;                          // [384][68] k-major, padded
    float* Xs = sm + FIN * WT_STR;           // [2][256][PROJ_XS]
    const int t = threadIdx.x;
    const int row0 = blockIdx.x * PROJ_BR;

    const unsigned int xs_smem =
        (unsigned int)__cvta_generic_to_shared(Xs);

    for (int e = t; e < (FIN * 64) / 4; e += 256) {
        float4 v = reinterpret_cast<const float4*>(W)[e];
        int flat = e * 4;
        int c = flat / FIN, k = flat % FIN;
        WT[(k + 0) * WT_STR + c] = v.x;
        WT[(k + 1) * WT_STR + c] = v.y;
        WT[(k + 2) * WT_STR + c] = v.z;
        WT[(k + 3) * WT_STR + c] = v.w;
    }

    auto issue_tile = [&](int kt, int buf) {
#pragma unroll
        for (int e = t; e < PROJ_BR * 4; e += 256) {
            int r = e >> 2, q = (e & 3) * 4;
            int grow = row0 + r;
            if (grow >= NP) grow = NP - 1;
            unsigned int dst = xs_smem +
                (unsigned int)((buf * PROJ_BR * PROJ_XS + r * PROJ_XS + q) * 4);
            cp_async16(dst, &X[(size_t)grow * FIN + kt + q]);
        }
        CP_COMMIT();
    };

    const int cg = t & 7;
    const int rg = t >> 3;

    unsigned long long acc[8][4];
#pragma unroll
    for (int i = 0; i < 8; i++)
#pragma unroll
        for (int j = 0; j < 4; j++) acc[i][j] = 0ull;

    issue_tile(0, 0);

    const int NIT = FIN / PROJ_KT;           // 24
    for (int it = 0; it < NIT; it++) {
        if (it + 1 < NIT) {
            issue_tile((it + 1) * PROJ_KT, (it + 1) & 1);
            CP_WAIT(1);
        } else {
            CP_WAIT(0);
        }
        __syncthreads();
        const float* Xb = Xs + (it & 1) * (PROJ_BR * PROJ_XS);
#pragma unroll
        for (int q = 0; q < 4; q++) {
            float4 xq[8];
#pragma unroll
            for (int i = 0; i < 8; i++)
                xq[i] = *(const float4*)&Xb[(rg + 32 * i) * PROJ_XS + q * 4];
#pragma unroll
            for (int kk = 0; kk < 4; kk++) {
                const int k = it * PROJ_KT + q * 4 + kk;
                const ulonglong2 w0 = *(const ulonglong2*)&WT[k * WT_STR + cg * 8];
                const ulonglong2 w1 = *(const ulonglong2*)&WT[k * WT_STR + cg * 8 + 4];
#pragma unroll
                for (int i = 0; i < 8; i++) {
                    unsigned long long xv =
                        bcast2(((const float*)&xq[i])[kk]);
                    acc[i][0] = ffma2(xv, w0.x, acc[i][0]);
                    acc[i][1] = ffma2(xv, w0.y, acc[i][1]);
                    acc[i][2] = ffma2(xv, w1.x, acc[i][2]);
                    acc[i][3] = ffma2(xv, w1.y, acc[i][3]);
                }
            }
        }
        __syncthreads();
    }

    float bias[8];
#pragma unroll
    for (int j = 0; j < 8; j++) bias[j] = b[cg * 8 + j];
#pragma unroll
    for (int i = 0; i < 8; i++) {
        int grow = row0 + rg + 32 * i;
        if (grow < NP) {
            float o[8];
#pragma unroll
            for (int j = 0; j < 4; j++) {
                float2 p = unpack2(acc[i][j]);
                o[2 * j]     = fmaxf(p.x + bias[2 * j], 0.f);
                o[2 * j + 1] = fmaxf(p.y + bias[2 * j + 1], 0.f);
            }
            float* dst = &g_x0[(size_t)grow * H + cg * 8];
            *(float4*)dst       = make_float4(o[0], o[1], o[2], o[3]);
            *(float4*)(dst + 4) = make_float4(o[4], o[5], o[6], o[7]);
        }
    }
}

// ---------------------------------------------------------------------------
// Launch 4: fill adjacency
// ---------------------------------------------------------------------------
__global__ void fill_kernel(const int* __restrict__ pbs, const int* __restrict__ pbd,
                            const int* __restrict__ pcs, const int* __restrict__ pcd,
                            const int* __restrict__ pss, const int* __restrict__ psd) {
    int i = blockIdx.x * 256 + threadIdx.x;
    if (i >= EE) return;
    int s, d;
    switch (blockIdx.y) {
        case 0:  s = pbs[i];        d = pbd[i] + BOFF; break;
        case 1:  s = pbd[i] + BOFF; d = pbs[i];        break;
        case 2:  s = pcs[i];        d = pcd[i] + COFF; break;
        case 3:  s = pcd[i] + COFF; d = pcs[i];        break;
        case 4:  s = pss[i];        d = psd[i] + SOFF; break;
        default: s = psd[i] + SOFF; d = pss[i];        break;
    }
    int pos = atomicAdd(&g_fill[d], 1);
    g_eidx[pos] = s;
}

// ---------------------------------------------------------------------------
// Launch 5: copy embeddings into g_x0 rows [NP, NTOT)
// ---------------------------------------------------------------------------
__global__ void init_kernel(const float* __restrict__ eb,
                            const float* __restrict__ ec,
                            const float* __restrict__ es) {
    int i = blockIdx.x * 256 + threadIdx.x;
    const int nb4 = NB * H / 4, nc4 = NCA * H / 4, ns4 = NSH * H / 4;
    if (i < nb4 + nc4 + ns4) {
        float4* dst = reinterpret_cast<float4*>(g_x0 + (size_t)NP * H);
        float4 v;
        if (i < nb4)              v = reinterpret_cast<const float4*>(eb)[i];
        else if (i < nb4 + nc4)   v = reinterpret_cast<const float4*>(ec)[i - nb4];
        else                      v = reinterpret_cast<const float4*>(es)[i - nb4 - nc4];
        dst[i] = v;
    }
}

// ---------------------------------------------------------------------------
// Launches 6/7: FUSED aggregate+combine.
// out = [relu]( (gather_mean(x)) @ Wl^T + bl + x @ Wr^T )
// The As-fill performs the CSR gather-sum directly (no g_agg round trip):
// 16 threads per row, each owning 4 cols, iterate the row's edge list.
// Mainloop identical to the quad-load combine.
// ---------------------------------------------------------------------------
#define CMB_WSTR 68
template <int OUT, bool RELU>
__global__ void fused_combine_kernel(const float* __restrict__ x,
                                     const float* __restrict__ Wl,
                                     const float* __restrict__ bl,
                                     const float* __restrict__ Wr,
                                     float* __restrict__ out) {
    constexpr int BR = 128;
    constexpr int COLG = OUT / 8;
    constexpr int RG = 256 / COLG;
    constexpr int R = BR / RG;
    constexpr int STR = 68;

    extern __shared__ float sm[];
    float* WlT = sm;
    float* WrT = WlT + 64 * CMB_WSTR;
    float* As  = WrT + 64 * CMB_WSTR;
    float* Xs  = As + BR * STR;

    const int t = threadIdx.x;
    for (int e = t; e < (OUT * 64) / 4; e += 256) {
        float4 vl = reinterpret_cast<const float4*>(Wl)[e];
        float4 vr = reinterpret_cast<const float4*>(Wr)[e];
        int flat = e * 4;
        int c = flat / 64, k = flat % 64;
        WlT[(k + 0) * CMB_WSTR + c] = vl.x;
        WlT[(k + 1) * CMB_WSTR + c] = vl.y;
        WlT[(k + 2) * CMB_WSTR + c] = vl.z;
        WlT[(k + 3) * CMB_WSTR + c] = vl.w;
        WrT[(k + 0) * CMB_WSTR + c] = vr.x;
        WrT[(k + 1) * CMB_WSTR + c] = vr.y;
        WrT[(k + 2) * CMB_WSTR + c] = vr.z;
        WrT[(k + 3) * CMB_WSTR + c] = vr.w;
    }

    const int row0 = blockIdx.x * BR;
    // fused gather: e covers (row r, col-quad q); 16 threads per row
    for (int e = t; e < BR * 16; e += 256) {
        int r = e >> 4, q = (e & 15) * 4;
        int grow = row0 + r;
        if (grow >= NTOT) grow = NTOT - 1;

        const int beg = g_row[grow];
        const int end = g_row[grow + 1];
        float4 acc = make_float4(0.f, 0.f, 0.f, 0.f);
        int j = beg;
        for (; j + 1 < end; j += 2) {
            int s0 = g_eidx[j], s1 = g_eidx[j + 1];
            float4 v0 = *(const float4*)&x[(size_t)s0 * H + q];
            float4 v1 = *(const float4*)&x[(size_t)s1 * H + q];
            acc.x += v0.x + v1.x;
            acc.y += v0.y + v1.y;
            acc.z += v0.z + v1.z;
            acc.w += v0.w + v1.w;
        }
        if (j < end) {
            int s0 = g_eidx[j];
            float4 v0 = *(const float4*)&x[(size_t)s0 * H + q];
            acc.x += v0.x; acc.y += v0.y; acc.z += v0.z; acc.w += v0.w;
        }
        float iv = g_deg[grow];
        acc.x *= iv; acc.y *= iv; acc.z *= iv; acc.w *= iv;
        *(float4*)&As[r * STR + q] = acc;
        *(float4*)&Xs[r * STR + q] = *(const float4*)&x[(size_t)grow * H + q];
    }
    __syncthreads();

    const int cg = t % COLG;
    const int rg = t / COLG;

    unsigned long long acc[R][4];
#pragma unroll
    for (int i = 0; i < R; i++)
#pragma unroll
        for (int j = 0; j < 4; j++) acc[i][j] = 0ull;

#pragma unroll
    for (int q = 0; q < 16; q++) {           // 64 k = 16 quads
        float4 aq[R], xq[R];
#pragma unroll
        for (int i = 0; i < R; i++) {
            const int r = rg + RG * i;
            aq[i] = *(const float4*)&As[r * STR + q * 4];
            xq[i] = *(const float4*)&Xs[r * STR + q * 4];
        }
#pragma unroll
        for (int kk = 0; kk < 4; kk++) {
            const int k = q * 4 + kk;
            const ulonglong2 wl0 = *(const ulonglong2*)&WlT[k * CMB_WSTR + cg * 8];
            const ulonglong2 wl1 = *(const ulonglong2*)&WlT[k * CMB_WSTR + cg * 8 + 4];
            const ulonglong2 wr0 = *(const ulonglong2*)&WrT[k * CMB_WSTR + cg * 8];
            const ulonglong2 wr1 = *(const ulonglong2*)&WrT[k * CMB_WSTR + cg * 8 + 4];
#pragma unroll
            for (int i = 0; i < R; i++) {
                unsigned long long a2 = bcast2(((const float*)&aq[i])[kk]);
                unsigned long long x2 = bcast2(((const float*)&xq[i])[kk]);
                acc[i][0] = ffma2(a2, wl0.x, acc[i][0]);
                acc[i][0] = ffma2(x2, wr0.x, acc[i][0]);
                acc[i][1] = ffma2(a2, wl0.y, acc[i][1]);
                acc[i][1] = ffma2(x2, wr0.y, acc[i][1]);
                acc[i][2] = ffma2(a2, wl1.x, acc[i][2]);
                acc[i][2] = ffma2(x2, wr1.x, acc[i][2]);
                acc[i][3] = ffma2(a2, wl1.y, acc[i][3]);
                acc[i][3] = ffma2(x2, wr1.y, acc[i][3]);
            }
        }
    }

    float bias[8];
#pragma unroll
    for (int j = 0; j < 8; j++) bias[j] = bl[cg * 8 + j];
#pragma unroll
    for (int i = 0; i < R; i++) {
        int grow = row0 + rg + RG * i;
        if (grow < NTOT) {
            float o[8];
#pragma unroll
            for (int j = 0; j < 4; j++) {
                float2 p = unpack2(acc[i][j]);
                float v0 = p.x + bias[2 * j];
                float v1 = p.y + bias[2 * j + 1];
                if (RELU) { v0 = fmaxf(v0, 0.f); v1 = fmaxf(v1, 0.f); }
                o[2 * j] = v0; o[2 * j + 1] = v1;
            }
            float* dst = &out[(size_t)grow * OUT + cg * 8];
            *(float4*)dst       = make_float4(o[0], o[1], o[2], o[3]);
            *(float4*)(dst + 4) = make_float4(o[4], o[5], o[6], o[7]);
        }
    }
}

// ---------------------------------------------------------------------------
// Host launch sequence. My kernel indices: zero(0) cnt(1) scan(2) proj(3)
// fill(4) init(5) fcmb1(6) fcmb2(7). Harness prepends 2; ncu -s 5 -c 1
// captures proj (idx 3).
// ---------------------------------------------------------------------------
extern "C" void kernel_launch(void* const* d_in, const int* in_sizes, int n_in,
                              void* d_out, int out_size) {
    (void)in_sizes; (void)n_in; (void)out_size;

    const float* x_product = (const float*)d_in[0];
    const int*   pb_src    = (const int*)d_in[1];
    const int*   pb_dst    = (const int*)d_in[2];
    const int*   pc_src    = (const int*)d_in[3];
    const int*   pc_dst    = (const int*)d_in[4];
    const int*   ps_src    = (const int*)d_in[5];
    const int*   ps_dst    = (const int*)d_in[6];
    const float* W_proj    = (const float*)d_in[7];
    const float* b_proj    = (const float*)d_in[8];
    const float* emb_b     = (const float*)d_in[9];
    const float* emb_c     = (const float*)d_in[10];
    const float* emb_s     = (const float*)d_in[11];
    const float* W1l       = (const float*)d_in[12];
    const float* b1l       = (const float*)d_in[13];
    const float* W1r       = (const float*)d_in[14];
    const float* W2l       = (const float*)d_in[15];
    const float* b2l       = (const float*)d_in[16];
    const float* W2r       = (const float*)d_in[17];
    float* out = (float*)d_out;

    float *px0, *ph1;
    cudaGetSymbolAddress((void**)&px0, g_x0);
    cudaGetSymbolAddress((void**)&ph1, g_h1);

    const int CMB_SMEM = (2 * 64 * CMB_WSTR + 2 * 128 * 68) * 4;   // 104448
    cudaFuncSetAttribute(proj_kernel,
                         cudaFuncAttributeMaxDynamicSharedMemorySize, PROJ_SMEM);
    cudaFuncSetAttribute(fused_combine_kernel<64, true>,
                         cudaFuncAttributeMaxDynamicSharedMemorySize, CMB_SMEM);
    cudaFuncSetAttribute(fused_combine_kernel<32, false>,
                         cudaFuncAttributeMaxDynamicSharedMemorySize, CMB_SMEM);

    const int ZRB = (NTOT + 255) / 256;
    const int CPB = ((NB + NCA + NSH) * H / 4 + 255) / 256;
    const int PRB = (NP + PROJ_BR - 1) / PROJ_BR;   // 1954
    const int CMB = (NTOT + 127) / 128;
    const dim3 EG((EE + 255) / 256, 6);

    zero_kernel<<<ZRB, 256>>>();
    cnt_kernel<<<EG, 256>>>(pb_src, pb_dst, pc_src, pc_dst, ps_src, ps_dst);
    scan_kernel<<<SCAN_NB, 1024>>>();
    proj_kernel<<<PRB, 256, PROJ_SMEM>>>(x_product, W_proj, b_proj);
    fill_kernel<<<EG, 256>>>(pb_src, pb_dst, pc_src, pc_dst, ps_src, ps_dst);
    init_kernel<<<CPB, 256>>>(emb_b, emb_c, emb_s);
    fused_combine_kernel<64, true><<<CMB, 256, CMB_SMEM>>>(px0, W1l, b1l, W1r, ph1);
    fused_combine_kernel<32, false><<<CMB, 256, CMB_SMEM>>>(ph1, W2l, b2l, W2r, out);
}

// round 15
// speedup vs baseline: 1.3331x; 1.3331x over previous
#include <cuda_runtime.h>
#include <cstdint>

// ---------------------------------------------------------------------------
// Problem constants
// ---------------------------------------------------------------------------
#define NP   500000
#define NB   20000
#define NCA  5000
#define NSH  2000
#define NTOT 527000
#define EE   500000
#define E6   (6 * EE)
#define H    64
#define ODIM 32
#define FIN  384

#define BOFF NP
#define COFF (NP + NB)
#define SOFF (NP + NB + NCA)

#define SCAN_NB ((NTOT + 1023) / 1024)

// ---------------------------------------------------------------------------
// Scratch (device globals: allocation-free rule)
// ---------------------------------------------------------------------------
__device__ float g_x0[(size_t)NTOT * H];
__device__ float g_h1[(size_t)NTOT * H];
__device__ float g_agg[(size_t)NTOT * H];
__device__ float g_deg[NTOT];
__device__ int   g_cnt[NTOT];
__device__ int   g_row[NTOT + 1];
__device__ int   g_fill[NTOT];
__device__ int   g_eidx[E6];
__device__ unsigned long long g_look[SCAN_NB];

// ---------------------------------------------------------------------------
// Side stream + events for fork-join overlap (created at binary load, before
// harness mem checkpoints; streams/events are not device-memory allocation).
// Falls back to fully serial null-stream execution if creation fails.
// ---------------------------------------------------------------------------
struct AuxStreams {
    cudaStream_t s2 = nullptr;
    cudaEvent_t  evFork = nullptr, evJoin = nullptr;
    AuxStreams() {
        if (cudaStreamCreateWithFlags(&s2, cudaStreamNonBlocking) != cudaSuccess)
            s2 = nullptr;
        if (s2) {
            if (cudaEventCreateWithFlags(&evFork, cudaEventDisableTiming) != cudaSuccess ||
                cudaEventCreateWithFlags(&evJoin, cudaEventDisableTiming) != cudaSuccess) {
                s2 = nullptr;
            }
        }
    }
};
static AuxStreams g_aux;

// ---------------------------------------------------------------------------
// f32x2 packed-FMA + cp.async helpers
// ---------------------------------------------------------------------------
__device__ __forceinline__ unsigned long long ffma2(unsigned long long a,
                                                    unsigned long long b,
                                                    unsigned long long c) {
    unsigned long long d;
    asm("fma.rn.f32x2 %0, %1, %2, %3;" : "=l"(d) : "l"(a), "l"(b), "l"(c));
    return d;
}
__device__ __forceinline__ unsigned long long bcast2(float v) {
    unsigned long long r;
    unsigned int u = __float_as_uint(v);
    asm("mov.b64 %0, {%1, %2};" : "=l"(r) : "r"(u), "r"(u));
    return r;
}
__device__ __forceinline__ float2 unpack2(unsigned long long v) {
    unsigned int lo, hi;
    asm("mov.b64 {%0, %1}, %2;" : "=r"(lo), "=r"(hi) : "l"(v));
    return make_float2(__uint_as_float(lo), __uint_as_float(hi));
}
__device__ __forceinline__ void cp_async16(unsigned int smem_dst, const void* gsrc) {
    asm volatile("cp.async.cg.shared.global [%0], [%1], 16;\n"
                 :: "r"(smem_dst), "l"(gsrc));
}
#define CP_COMMIT()  asm volatile("cp.async.commit_group;\n" ::: "memory")
#define CP_WAIT(n)   asm volatile("cp.async.wait_group %0;\n" :: "n"(n) : "memory")

// ---------------------------------------------------------------------------
// zero counts + lookback words
// ---------------------------------------------------------------------------
__global__ void zero_kernel() {
    int i = blockIdx.x * 256 + threadIdx.x;
    if (i < NTOT) g_cnt[i] = 0;
    if (i < SCAN_NB) g_look[i] = 0ull;
}

// ---------------------------------------------------------------------------
// in-degree counts. blockIdx.y = relation id (0..5).
// ---------------------------------------------------------------------------
__global__ void cnt_kernel(const int* __restrict__ pbs, const int* __restrict__ pbd,
                           const int* __restrict__ pcs, const int* __restrict__ pcd,
                           const int* __restrict__ pss, const int* __restrict__ psd) {
    int i = blockIdx.x * 256 + threadIdx.x;
    if (i >= EE) return;
    int d;
    switch (blockIdx.y) {
        case 0:  d = pbd[i] + BOFF; break;
        case 1:  d = pbs[i];        break;
        case 2:  d = pcd[i] + COFF; break;
        case 3:  d = pcs[i];        break;
        case 4:  d = psd[i] + SOFF; break;
        default: d = pss[i];        break;
    }
    atomicAdd(&g_cnt[d], 1);
}

// ---------------------------------------------------------------------------
// decoupled-lookback exclusive scan (row starts, fill cursors, 1/deg)
// ---------------------------------------------------------------------------
__global__ void scan_kernel() {
    __shared__ int sb[1024];
    __shared__ int s_base;
    const int t = threadIdx.x;
    const int bid = blockIdx.x;
    const int i = bid * 1024 + t;

    int c = (i < NTOT) ? g_cnt[i] : 0;
    sb[t] = c;
    __syncthreads();
    for (int off = 1; off < 1024; off <<= 1) {
        int u = (t >= off) ? sb[t - off] : 0;
        __syncthreads();
        sb[t] += u;
        __syncthreads();
    }
    const int incl = sb[t];
    const int aggregate = sb[1023];

    if (t == 0) {
        unsigned long long st = (bid == 0) ? 2ull : 1ull;
        atomicExch(&g_look[bid], (st << 32) | (unsigned int)aggregate);
    }

    if (bid == 0) {
        if (t == 0) s_base = 0;
    } else if (t < 32) {
        int acc = 0;
        int windowEnd = bid - 1;
        while (true) {
            int p = windowEnd - t;
            unsigned long long w = 0;
            if (p >= 0) w = atomicAdd(&g_look[p], 0ull);
            unsigned int st  = (p >= 0) ? (unsigned int)(w >> 32) : 2u;
            int val          = (p >= 0) ? (int)(unsigned int)w : 0;
            unsigned int ready = __ballot_sync(0xffffffffu, st != 0u);
            if (ready != 0xffffffffu) continue;
            unsigned int haveIncl = __ballot_sync(0xffffffffu, st == 2u);
            if (haveIncl) {
                int L = __ffs(haveIncl) - 1;
                int contrib = (t <= L) ? val : 0;
#pragma unroll
                for (int o = 16; o; o >>= 1)
                    contrib += __shfl_xor_sync(0xffffffffu, contrib, o);
                acc += contrib;
                break;
            } else {
                int contrib = val;
#pragma unroll
                for (int o = 16; o; o >>= 1)
                    contrib += __shfl_xor_sync(0xffffffffu, contrib, o);
                acc += contrib;
                windowEnd -= 32;
            }
        }
        if (t == 0) {
            s_base = acc;
            atomicExch(&g_look[bid],
                       (2ull << 32) | (unsigned int)(acc + aggregate));
        }
    }
    __syncthreads();
    const int base = s_base;

    if (i < NTOT) {
        int excl = base + incl - c;
        g_row[i]  = excl;
        g_fill[i] = excl;
        g_deg[i]  = 1.0f / fmaxf((float)c, 1.0f);
    }
    if (i == NTOT - 1) g_row[NTOT] = E6;
}

// ---------------------------------------------------------------------------
// fill adjacency
// ---------------------------------------------------------------------------
__global__ void fill_kernel(const int* __restrict__ pbs, const int* __restrict__ pbd,
                            const int* __restrict__ pcs, const int* __restrict__ pcd,
                            const int* __restrict__ pss, const int* __restrict__ psd) {
    int i = blockIdx.x * 256 + threadIdx.x;
    if (i >= EE) return;
    int s, d;
    switch (blockIdx.y) {
        case 0:  s = pbs[i];        d = pbd[i] + BOFF; break;
        case 1:  s = pbd[i] + BOFF; d = pbs[i];        break;
        case 2:  s = pcs[i];        d = pcd[i] + COFF; break;
        case 3:  s = pcd[i] + COFF; d = pcs[i];        break;
        case 4:  s = pss[i];        d = psd[i] + SOFF; break;
        default: s = psd[i] + SOFF; d = pss[i];        break;
    }
    int pos = atomicAdd(&g_fill[d], 1);
    g_eidx[pos] = s;
}

// ---------------------------------------------------------------------------
// copy embeddings into g_x0 rows [NP, NTOT)
// ---------------------------------------------------------------------------
__global__ void init_kernel(const float* __restrict__ eb,
                            const float* __restrict__ ec,
                            const float* __restrict__ es) {
    int i = blockIdx.x * 256 + threadIdx.x;
    const int nb4 = NB * H / 4, nc4 = NCA * H / 4, ns4 = NSH * H / 4;
    if (i < nb4 + nc4 + ns4) {
        float4* dst = reinterpret_cast<float4*>(g_x0 + (size_t)NP * H);
        float4 v;
        if (i < nb4)              v = reinterpret_cast<const float4*>(eb)[i];
        else if (i < nb4 + nc4)   v = reinterpret_cast<const float4*>(ec)[i - nb4];
        else                      v = reinterpret_cast<const float4*>(es)[i - nb4 - nc4];
        dst[i] = v;
    }
}

// ---------------------------------------------------------------------------
// projection v4 (R9 champion, 649us verified): crossbar/FMA balance point.
// g_x0[0:NP] = relu(x_product @ W_proj^T + b_proj)
// 256 threads, 256 rows/block, 8 rows x 8 cols per thread, FFMA2.
// ---------------------------------------------------------------------------
#define PROJ_BR 256
#define PROJ_KT 16
#define PROJ_XS 20
#define WT_STR  68
#define PROJ_SMEM ((FIN * WT_STR + 2 * PROJ_BR * PROJ_XS) * 4)   // 145408 B

__global__ void __launch_bounds__(256, 1)
proj_kernel(const float* __restrict__ X,
            const float* __restrict__ W,
            const float* __restrict__ b) {
    extern __shared__ float sm[];
    float* WT = sm;                          // [384][68] k-major, padded
    float* Xs = sm + FIN * WT_STR;           // [2][256][PROJ_XS]
    const int t = threadIdx.x;
    const int row0 = blockIdx.x * PROJ_BR;

    const unsigned int xs_smem =
        (unsigned int)__cvta_generic_to_shared(Xs);

    for (int e = t; e < (FIN * 64) / 4; e += 256) {
        float4 v = reinterpret_cast<const float4*>(W)[e];
        int flat = e * 4;
        int c = flat / FIN, k = flat % FIN;
        WT[(k + 0) * WT_STR + c] = v.x;
        WT[(k + 1) * WT_STR + c] = v.y;
        WT[(k + 2) * WT_STR + c] = v.z;
        WT[(k + 3) * WT_STR + c] = v.w;
    }

    auto issue_tile = [&](int kt, int buf) {
#pragma unroll
        for (int e = t; e < PROJ_BR * 4; e += 256) {
            int r = e >> 2, q = (e & 3) * 4;
            int grow = row0 + r;
            if (grow >= NP) grow = NP - 1;
            unsigned int dst = xs_smem +
                (unsigned int)((buf * PROJ_BR * PROJ_XS + r * PROJ_XS + q) * 4);
            cp_async16(dst, &X[(size_t)grow * FIN + kt + q]);
        }
        CP_COMMIT();
    };

    const int cg = t & 7;
    const int rg = t >> 3;

    unsigned long long acc[8][4];
#pragma unroll
    for (int i = 0; i < 8; i++)
#pragma unroll
        for (int j = 0; j < 4; j++) acc[i][j] = 0ull;

    issue_tile(0, 0);

    const int NIT = FIN / PROJ_KT;           // 24
    for (int it = 0; it < NIT; it++) {
        if (it + 1 < NIT) {
            issue_tile((it + 1) * PROJ_KT, (it + 1) & 1);
            CP_WAIT(1);
        } else {
            CP_WAIT(0);
        }
        __syncthreads();
        const float* Xb = Xs + (it & 1) * (PROJ_BR * PROJ_XS);
#pragma unroll
        for (int q = 0; q < 4; q++) {
            float4 xq[8];
#pragma unroll
            for (int i = 0; i < 8; i++)
                xq[i] = *(const float4*)&Xb[(rg + 32 * i) * PROJ_XS + q * 4];
#pragma unroll
            for (int kk = 0; kk < 4; kk++) {
                const int k = it * PROJ_KT + q * 4 + kk;
                const ulonglong2 w0 = *(const ulonglong2*)&WT[k * WT_STR + cg * 8];
                const ulonglong2 w1 = *(const ulonglong2*)&WT[k * WT_STR + cg * 8 + 4];
#pragma unroll
                for (int i = 0; i < 8; i++) {
                    unsigned long long xv =
                        bcast2(((const float*)&xq[i])[kk]);
                    acc[i][0] = ffma2(xv, w0.x, acc[i][0]);
                    acc[i][1] = ffma2(xv, w0.y, acc[i][1]);
                    acc[i][2] = ffma2(xv, w1.x, acc[i][2]);
                    acc[i][3] = ffma2(xv, w1.y, acc[i][3]);
                }
            }
        }
        __syncthreads();
    }

    float bias[8];
#pragma unroll
    for (int j = 0; j < 8; j++) bias[j] = b[cg * 8 + j];
#pragma unroll
    for (int i = 0; i < 8; i++) {
        int grow = row0 + rg + 32 * i;
        if (grow < NP) {
            float o[8];
#pragma unroll
            for (int j = 0; j < 4; j++) {
                float2 p = unpack2(acc[i][j]);
                o[2 * j]     = fmaxf(p.x + bias[2 * j], 0.f);
                o[2 * j + 1] = fmaxf(p.y + bias[2 * j + 1], 0.f);
            }
            float* dst = &g_x0[(size_t)grow * H + cg * 8];
            *(float4*)dst       = make_float4(o[0], o[1], o[2], o[3]);
            *(float4*)(dst + 4) = make_float4(o[4], o[5], o[6], o[7]);
        }
    }
}

// ---------------------------------------------------------------------------
// atomic-free aggregation (R9 version; 527k warps for latency hiding).
// NOW writes the MEAN directly (pre-scaled by 1/deg).
// ---------------------------------------------------------------------------
__global__ void agg_kernel(const float* __restrict__ x) {
    int w = (blockIdx.x * blockDim.x + threadIdx.x) >> 5;
    if (w >= NTOT) return;
    const int lane = threadIdx.x & 31;
    const int half = lane >> 4;
    const int li   = lane & 15;
    const size_t co = (size_t)(li * 4);

    const int beg = g_row[w];
    const int end = g_row[w + 1];

    float4 acc = make_float4(0.f, 0.f, 0.f, 0.f);

    int j = beg + half;
    for (; j + 6 < end; j += 8) {
        int s0 = g_eidx[j];
        int s1 = g_eidx[j + 2];
        int s2 = g_eidx[j + 4];
        int s3 = g_eidx[j + 6];
        float4 v0 = *(const float4*)&x[(size_t)s0 * H + co];
        float4 v1 = *(const float4*)&x[(size_t)s1 * H + co];
        float4 v2 = *(const float4*)&x[(size_t)s2 * H + co];
        float4 v3 = *(const float4*)&x[(size_t)s3 * H + co];
        acc.x += v0.x + v1.x + v2.x + v3.x;
        acc.y += v0.y + v1.y + v2.y + v3.y;
        acc.z += v0.z + v1.z + v2.z + v3.z;
        acc.w += v0.w + v1.w + v2.w + v3.w;
    }
    for (; j < end; j += 2) {
        int s = g_eidx[j];
        float4 v = *(const float4*)&x[(size_t)s * H + co];
        acc.x += v.x; acc.y += v.y; acc.z += v.z; acc.w += v.w;
    }

    acc.x += __shfl_xor_sync(0xffffffffu, acc.x, 16);
    acc.y += __shfl_xor_sync(0xffffffffu, acc.y, 16);
    acc.z += __shfl_xor_sync(0xffffffffu, acc.z, 16);
    acc.w += __shfl_xor_sync(0xffffffffu, acc.w, 16);

    if (half == 0) {
        float iv = g_deg[w];
        acc.x *= iv; acc.y *= iv; acc.z *= iv; acc.w *= iv;
        *(float4*)&g_agg[(size_t)w * H + co] = acc;
    }
}

// ---------------------------------------------------------------------------
// SAGE combine (quad a/x loads; agg already holds the mean)
// out = [relu]( agg @ Wl^T + bl + x @ Wr^T )
// ---------------------------------------------------------------------------
#define CMB_WSTR 68
template <int OUT, bool RELU>
__global__ void combine_kernel(const float* __restrict__ agg,
                               const float* __restrict__ x,
                               const float* __restrict__ Wl,
                               const float* __restrict__ bl,
                               const float* __restrict__ Wr,
                               float* __restrict__ out) {
    constexpr int BR = 128;
    constexpr int COLG = OUT / 8;
    constexpr int RG = 256 / COLG;
    constexpr int R = BR / RG;
    constexpr int STR = 68;

    extern __shared__ float sm[];
    float* WlT = sm;
    float* WrT = WlT + 64 * CMB_WSTR;
    float* As  = WrT + 64 * CMB_WSTR;
    float* Xs  = As + BR * STR;

    const int t = threadIdx.x;
    for (int e = t; e < (OUT * 64) / 4; e += 256) {
        float4 vl = reinterpret_cast<const float4*>(Wl)[e];
        float4 vr = reinterpret_cast<const float4*>(Wr)[e];
        int flat = e * 4;
        int c = flat / 64, k = flat % 64;
        WlT[(k + 0) * CMB_WSTR + c] = vl.x;
        WlT[(k + 1) * CMB_WSTR + c] = vl.y;
        WlT[(k + 2) * CMB_WSTR + c] = vl.z;
        WlT[(k + 3) * CMB_WSTR + c] = vl.w;
        WrT[(k + 0) * CMB_WSTR + c] = vr.x;
        WrT[(k + 1) * CMB_WSTR + c] = vr.y;
        WrT[(k + 2) * CMB_WSTR + c] = vr.z;
        WrT[(k + 3) * CMB_WSTR + c] = vr.w;
    }

    const int row0 = blockIdx.x * BR;
    for (int e = t; e < BR * 16; e += 256) {
        int r = e >> 4, q = (e & 15) * 4;
        int grow = row0 + r;
        if (grow >= NTOT) grow = NTOT - 1;
        *(float4*)&As[r * STR + q] = *(const float4*)&agg[(size_t)grow * H + q];
        *(float4*)&Xs[r * STR + q] = *(const float4*)&x[(size_t)grow * H + q];
    }
    __syncthreads();

    const int cg = t % COLG;
    const int rg = t / COLG;

    unsigned long long acc[R][4];
#pragma unroll
    for (int i = 0; i < R; i++)
#pragma unroll
        for (int j = 0; j < 4; j++) acc[i][j] = 0ull;

#pragma unroll
    for (int q = 0; q < 16; q++) {           // 64 k = 16 quads
        float4 aq[R], xq[R];
#pragma unroll
        for (int i = 0; i < R; i++) {
            const int r = rg + RG * i;
            aq[i] = *(const float4*)&As[r * STR + q * 4];
            xq[i] = *(const float4*)&Xs[r * STR + q * 4];
        }
#pragma unroll
        for (int kk = 0; kk < 4; kk++) {
            const int k = q * 4 + kk;
            const ulonglong2 wl0 = *(const ulonglong2*)&WlT[k * CMB_WSTR + cg * 8];
            const ulonglong2 wl1 = *(const ulonglong2*)&WlT[k * CMB_WSTR + cg * 8 + 4];
            const ulonglong2 wr0 = *(const ulonglong2*)&WrT[k * CMB_WSTR + cg * 8];
            const ulonglong2 wr1 = *(const ulonglong2*)&WrT[k * CMB_WSTR + cg * 8 + 4];
#pragma unroll
            for (int i = 0; i < R; i++) {
                unsigned long long a2 = bcast2(((const float*)&aq[i])[kk]);
                unsigned long long x2 = bcast2(((const float*)&xq[i])[kk]);
                acc[i][0] = ffma2(a2, wl0.x, acc[i][0]);
                acc[i][0] = ffma2(x2, wr0.x, acc[i][0]);
                acc[i][1] = ffma2(a2, wl0.y, acc[i][1]);
                acc[i][1] = ffma2(x2, wr0.y, acc[i][1]);
                acc[i][2] = ffma2(a2, wl1.x, acc[i][2]);
                acc[i][2] = ffma2(x2, wr1.x, acc[i][2]);
                acc[i][3] = ffma2(a2, wl1.y, acc[i][3]);
                acc[i][3] = ffma2(x2, wr1.y, acc[i][3]);
            }
        }
    }

    float bias[8];
#pragma unroll
    for (int j = 0; j < 8; j++) bias[j] = bl[cg * 8 + j];
#pragma unroll
    for (int i = 0; i < R; i++) {
        int grow = row0 + rg + RG * i;
        if (grow < NTOT) {
            float o[8];
#pragma unroll
            for (int j = 0; j < 4; j++) {
                float2 p = unpack2(acc[i][j]);
                float v0 = p.x + bias[2 * j];
                float v1 = p.y + bias[2 * j + 1];
                if (RELU) { v0 = fmaxf(v0, 0.f); v1 = fmaxf(v1, 0.f); }
                o[2 * j] = v0; o[2 * j + 1] = v1;
            }
            float* dst = &out[(size_t)grow * OUT + cg * 8];
            *(float4*)dst       = make_float4(o[0], o[1], o[2], o[3]);
            *(float4*)(dst + 4) = make_float4(o[4], o[5], o[6], o[7]);
        }
    }
}

// ---------------------------------------------------------------------------
// Host launch sequence (graph-capturable, allocation-free).
// Fork-join: CSR build (zero,cnt,scan,fill) + init run on a non-blocking
// side stream CONCURRENTLY with proj (proj has occ 12.5% and no smem left,
// but plenty of free warp slots for the small CSR blocks).
//   main:  evFork -> proj ------------------ waitEvent(evJoin) -> agg1 ...
//   side:  waitEvent(evFork) -> zero -> cnt -> scan -> fill -> init -> evJoin
// Falls back to fully serial if stream creation failed.
// ---------------------------------------------------------------------------
extern "C" void kernel_launch(void* const* d_in, const int* in_sizes, int n_in,
                              void* d_out, int out_size) {
    (void)in_sizes; (void)n_in; (void)out_size;

    const float* x_product = (const float*)d_in[0];
    const int*   pb_src    = (const int*)d_in[1];
    const int*   pb_dst    = (const int*)d_in[2];
    const int*   pc_src    = (const int*)d_in[3];
    const int*   pc_dst    = (const int*)d_in[4];
    const int*   ps_src    = (const int*)d_in[5];
    const int*   ps_dst    = (const int*)d_in[6];
    const float* W_proj    = (const float*)d_in[7];
    const float* b_proj    = (const float*)d_in[8];
    const float* emb_b     = (const float*)d_in[9];
    const float* emb_c     = (const float*)d_in[10];
    const float* emb_s     = (const float*)d_in[11];
    const float* W1l       = (const float*)d_in[12];
    const float* b1l       = (const float*)d_in[13];
    const float* W1r       = (const float*)d_in[14];
    const float* W2l       = (const float*)d_in[15];
    const float* b2l       = (const float*)d_in[16];
    const float* W2r       = (const float*)d_in[17];
    float* out = (float*)d_out;

    float *px0, *ph1, *pagg;
    cudaGetSymbolAddress((void**)&px0, g_x0);
    cudaGetSymbolAddress((void**)&ph1, g_h1);
    cudaGetSymbolAddress((void**)&pagg, g_agg);

    const int CMB_SMEM = (2 * 64 * CMB_WSTR + 2 * 128 * 68) * 4;   // 104448
    cudaFuncSetAttribute(proj_kernel,
                         cudaFuncAttributeMaxDynamicSharedMemorySize, PROJ_SMEM);
    cudaFuncSetAttribute(combine_kernel<64, true>,
                         cudaFuncAttributeMaxDynamicSharedMemorySize, CMB_SMEM);
    cudaFuncSetAttribute(combine_kernel<32, false>,
                         cudaFuncAttributeMaxDynamicSharedMemorySize, CMB_SMEM);

    const int ZRB = (NTOT + 255) / 256;
    const int CPB = ((NB + NCA + NSH) * H / 4 + 255) / 256;
    const int PRB = (NP + PROJ_BR - 1) / PROJ_BR;   // 1954
    const int CMB = (NTOT + 127) / 128;
    const int AGB = (NTOT + 7) / 8;
    const dim3 EG((EE + 255) / 256, 6);

    if (g_aux.s2) {
        cudaStream_t s2 = g_aux.s2;
        cudaEventRecord(g_aux.evFork, 0);
        cudaStreamWaitEvent(s2, g_aux.evFork, 0);
        // side chain: CSR build + embedding copy
        zero_kernel<<<ZRB, 256, 0, s2>>>();
        cnt_kernel<<<EG, 256, 0, s2>>>(pb_src, pb_dst, pc_src, pc_dst, ps_src, ps_dst);
        scan_kernel<<<SCAN_NB, 1024, 0, s2>>>();
        fill_kernel<<<EG, 256, 0, s2>>>(pb_src, pb_dst, pc_src, pc_dst, ps_src, ps_dst);
        init_kernel<<<CPB, 256, 0, s2>>>(emb_b, emb_c, emb_s);
        cudaEventRecord(g_aux.evJoin, s2);
        // main: projection runs concurrently with the side chain
        proj_kernel<<<PRB, 256, PROJ_SMEM>>>(x_product, W_proj, b_proj);
        cudaStreamWaitEvent(0, g_aux.evJoin, 0);
    } else {
        // serial fallback (R9 ordering)
        zero_kernel<<<ZRB, 256>>>();
        cnt_kernel<<<EG, 256>>>(pb_src, pb_dst, pc_src, pc_dst, ps_src, ps_dst);
        scan_kernel<<<SCAN_NB, 1024>>>();
        proj_kernel<<<PRB, 256, PROJ_SMEM>>>(x_product, W_proj, b_proj);
        fill_kernel<<<EG, 256>>>(pb_src, pb_dst, pc_src, pc_dst, ps_src, ps_dst);
        init_kernel<<<CPB, 256>>>(emb_b, emb_c, emb_s);
    }

    // layers (null stream, after join)
    agg_kernel<<<AGB, 256>>>(px0);
    combine_kernel<64, true><<<CMB, 256, CMB_SMEM>>>(pagg, px0, W1l, b1l, W1r, ph1);
    agg_kernel<<<AGB, 256>>>(ph1);
    combine_kernel<32, false><<<CMB, 256, CMB_SMEM>>>(pagg, ph1, W2l, b2l, W2r, out);
}

// round 16
// speedup vs baseline: 1.3672x; 1.0256x over previous
#include <cuda_runtime.h>
#include <cstdint>

// ---------------------------------------------------------------------------
// Problem constants
// ---------------------------------------------------------------------------
#define NP   500000
#define NB   20000
#define NCA  5000
#define NSH  2000
#define NTOT 527000
#define EE   500000
#define E6   (6 * EE)
#define H    64
#define ODIM 32
#define FIN  384

#define BOFF NP
#define COFF (NP + NB)
#define SOFF (NP + NB + NCA)

#define SCAN_NB ((NTOT + 1023) / 1024)

// ---------------------------------------------------------------------------
// Scratch (device globals: allocation-free rule)
// ---------------------------------------------------------------------------
__device__ float g_x0[(size_t)NTOT * H];
__device__ float g_h1[(size_t)NTOT * H];
__device__ float g_agg[(size_t)NTOT * H];
__device__ float g_deg[NTOT];
__device__ int   g_cnt[NTOT];
__device__ int   g_row[NTOT + 1];
__device__ int   g_fill[NTOT];
__device__ int   g_eidx[E6];
__device__ unsigned long long g_look[SCAN_NB];

// ---------------------------------------------------------------------------
// Side stream + events for fork-join overlap (created at binary load).
// Falls back to fully serial null-stream execution if creation fails.
// ---------------------------------------------------------------------------
struct AuxStreams {
    cudaStream_t s2 = nullptr;
    cudaEvent_t  evFork = nullptr, evJoin = nullptr;
    AuxStreams() {
        if (cudaStreamCreateWithFlags(&s2, cudaStreamNonBlocking) != cudaSuccess)
            s2 = nullptr;
        if (s2) {
            if (cudaEventCreateWithFlags(&evFork, cudaEventDisableTiming) != cudaSuccess ||
                cudaEventCreateWithFlags(&evJoin, cudaEventDisableTiming) != cudaSuccess) {
                s2 = nullptr;
            }
        }
    }
};
static AuxStreams g_aux;

// ---------------------------------------------------------------------------
// f32x2 packed-FMA + cp.async helpers
// ---------------------------------------------------------------------------
__device__ __forceinline__ unsigned long long ffma2(unsigned long long a,
                                                    unsigned long long b,
                                                    unsigned long long c) {
    unsigned long long d;
    asm("fma.rn.f32x2 %0, %1, %2, %3;" : "=l"(d) : "l"(a), "l"(b), "l"(c));
    return d;
}
__device__ __forceinline__ unsigned long long bcast2(float v) {
    unsigned long long r;
    unsigned int u = __float_as_uint(v);
    asm("mov.b64 %0, {%1, %2};" : "=l"(r) : "r"(u), "r"(u));
    return r;
}
__device__ __forceinline__ float2 unpack2(unsigned long long v) {
    unsigned int lo, hi;
    asm("mov.b64 {%0, %1}, %2;" : "=r"(lo), "=r"(hi) : "l"(v));
    return make_float2(__uint_as_float(lo), __uint_as_float(hi));
}
__device__ __forceinline__ void cp_async16(unsigned int smem_dst, const void* gsrc) {
    asm volatile("cp.async.cg.shared.global [%0], [%1], 16;\n"
                 :: "r"(smem_dst), "l"(gsrc));
}
#define CP_COMMIT()  asm volatile("cp.async.commit_group;\n" ::: "memory")
#define CP_WAIT(n)   asm volatile("cp.async.wait_group %0;\n" :: "n"(n) : "memory")

// ---------------------------------------------------------------------------
// zero counts + lookback words
// ---------------------------------------------------------------------------
__global__ void zero_kernel() {
    int i = blockIdx.x * 256 + threadIdx.x;
    if (i < NTOT) g_cnt[i] = 0;
    if (i < SCAN_NB) g_look[i] = 0ull;
}

// ---------------------------------------------------------------------------
// in-degree counts. blockIdx.y = relation id (0..5).
// ---------------------------------------------------------------------------
__global__ void cnt_kernel(const int* __restrict__ pbs, const int* __restrict__ pbd,
                           const int* __restrict__ pcs, const int* __restrict__ pcd,
                           const int* __restrict__ pss, const int* __restrict__ psd) {
    int i = blockIdx.x * 256 + threadIdx.x;
    if (i >= EE) return;
    int d;
    switch (blockIdx.y) {
        case 0:  d = pbd[i] + BOFF; break;
        case 1:  d = pbs[i];        break;
        case 2:  d = pcd[i] + COFF; break;
        case 3:  d = pcs[i];        break;
        case 4:  d = psd[i] + SOFF; break;
        default: d = pss[i];        break;
    }
    atomicAdd(&g_cnt[d], 1);
}

// ---------------------------------------------------------------------------
// decoupled-lookback exclusive scan (row starts, fill cursors, 1/deg)
// ---------------------------------------------------------------------------
__global__ void scan_kernel() {
    __shared__ int sb[1024];
    __shared__ int s_base;
    const int t = threadIdx.x;
    const int bid = blockIdx.x;
    const int i = bid * 1024 + t;

    int c = (i < NTOT) ? g_cnt[i] : 0;
    sb[t] = c;
    __syncthreads();
    for (int off = 1; off < 1024; off <<= 1) {
        int u = (t >= off) ? sb[t - off] : 0;
        __syncthreads();
        sb[t] += u;
        __syncthreads();
    }
    const int incl = sb[t];
    const int aggregate = sb[1023];

    if (t == 0) {
        unsigned long long st = (bid == 0) ? 2ull : 1ull;
        atomicExch(&g_look[bid], (st << 32) | (unsigned int)aggregate);
    }

    if (bid == 0) {
        if (t == 0) s_base = 0;
    } else if (t < 32) {
        int acc = 0;
        int windowEnd = bid - 1;
        while (true) {
            int p = windowEnd - t;
            unsigned long long w = 0;
            if (p >= 0) w = atomicAdd(&g_look[p], 0ull);
            unsigned int st  = (p >= 0) ? (unsigned int)(w >> 32) : 2u;
            int val          = (p >= 0) ? (int)(unsigned int)w : 0;
            unsigned int ready = __ballot_sync(0xffffffffu, st != 0u);
            if (ready != 0xffffffffu) continue;
            unsigned int haveIncl = __ballot_sync(0xffffffffu, st == 2u);
            if (haveIncl) {
                int L = __ffs(haveIncl) - 1;
                int contrib = (t <= L) ? val : 0;
#pragma unroll
                for (int o = 16; o; o >>= 1)
                    contrib += __shfl_xor_sync(0xffffffffu, contrib, o);
                acc += contrib;
                break;
            } else {
                int contrib = val;
#pragma unroll
                for (int o = 16; o; o >>= 1)
                    contrib += __shfl_xor_sync(0xffffffffu, contrib, o);
                acc += contrib;
                windowEnd -= 32;
            }
        }
        if (t == 0) {
            s_base = acc;
            atomicExch(&g_look[bid],
                       (2ull << 32) | (unsigned int)(acc + aggregate));
        }
    }
    __syncthreads();
    const int base = s_base;

    if (i < NTOT) {
        int excl = base + incl - c;
        g_row[i]  = excl;
        g_fill[i] = excl;
        g_deg[i]  = 1.0f / fmaxf((float)c, 1.0f);
    }
    if (i == NTOT - 1) g_row[NTOT] = E6;
}

// ---------------------------------------------------------------------------
// fill adjacency
// ---------------------------------------------------------------------------
__global__ void fill_kernel(const int* __restrict__ pbs, const int* __restrict__ pbd,
                            const int* __restrict__ pcs, const int* __restrict__ pcd,
                            const int* __restrict__ pss, const int* __restrict__ psd) {
    int i = blockIdx.x * 256 + threadIdx.x;
    if (i >= EE) return;
    int s, d;
    switch (blockIdx.y) {
        case 0:  s = pbs[i];        d = pbd[i] + BOFF; break;
        case 1:  s = pbd[i] + BOFF; d = pbs[i];        break;
        case 2:  s = pcs[i];        d = pcd[i] + COFF; break;
        case 3:  s = pcd[i] + COFF; d = pcs[i];        break;
        case 4:  s = pss[i];        d = psd[i] + SOFF; break;
        default: s = psd[i] + SOFF; d = pss[i];        break;
    }
    int pos = atomicAdd(&g_fill[d], 1);
    g_eidx[pos] = s;
}

// ---------------------------------------------------------------------------
// copy embeddings into g_x0 rows [NP, NTOT)
// ---------------------------------------------------------------------------
__global__ void init_kernel(const float* __restrict__ eb,
                            const float* __restrict__ ec,
                            const float* __restrict__ es) {
    int i = blockIdx.x * 256 + threadIdx.x;
    const int nb4 = NB * H / 4, nc4 = NCA * H / 4, ns4 = NSH * H / 4;
    if (i < nb4 + nc4 + ns4) {
        float4* dst = reinterpret_cast<float4*>(g_x0 + (size_t)NP * H);
        float4 v;
        if (i < nb4)              v = reinterpret_cast<const float4*>(eb)[i];
        else if (i < nb4 + nc4)   v = reinterpret_cast<const float4*>(ec)[i - nb4];
        else                      v = reinterpret_cast<const float4*>(es)[i - nb4 - nc4];
        dst[i] = v;
    }
}

// ---------------------------------------------------------------------------
// projection v7: v4 mainloop with 128-BYTE k-tiles (PROJ_KT=32) so every
// DRAM fetch is a full L2 line (v4's 64B chunks wasted half of each line,
// ~2x DRAM amplification at ~580MB/wave working set >> L2).
// g_x0[0:NP] = relu(x_product @ W_proj^T + b_proj)
// 256 threads, 256 rows/block, 8 rows x 8 cols per thread, FFMA2.
// ---------------------------------------------------------------------------
#define PROJ_BR 256
#define PROJ_KT 32
#define PROJ_XS 36      // 32 data + 4 pad: quad addresses land on distinct banks
#define WT_STR  68
#define PROJ_SMEM ((FIN * WT_STR + 2 * PROJ_BR * PROJ_XS) * 4)   // 178176 B

__global__ void __launch_bounds__(256, 1)
proj_kernel(const float* __restrict__ X,
            const float* __restrict__ W,
            const float* __restrict__ b) {
    extern __shared__ float sm[];
    float* WT = sm;                          // [384][68] k-major, padded
    float* Xs = sm + FIN * WT_STR;           // [2][256][PROJ_XS]
    const int t = threadIdx.x;
    const int row0 = blockIdx.x * PROJ_BR;

    const unsigned int xs_smem =
        (unsigned int)__cvta_generic_to_shared(Xs);

    for (int e = t; e < (FIN * 64) / 4; e += 256) {
        float4 v = reinterpret_cast<const float4*>(W)[e];
        int flat = e * 4;
        int c = flat / FIN, k = flat % FIN;
        WT[(k + 0) * WT_STR + c] = v.x;
        WT[(k + 1) * WT_STR + c] = v.y;
        WT[(k + 2) * WT_STR + c] = v.z;
        WT[(k + 3) * WT_STR + c] = v.w;
    }

    // one 32-k (128 B/row) tile of X into buffer buf: 2048 cp.async16
    auto issue_tile = [&](int kt, int buf) {
#pragma unroll
        for (int e = t; e < PROJ_BR * 8; e += 256) {
            int r = e >> 3, q = (e & 7) * 4;
            int grow = row0 + r;
            if (grow >= NP) grow = NP - 1;
            unsigned int dst = xs_smem +
                (unsigned int)((buf * PROJ_BR * PROJ_XS + r * PROJ_XS + q) * 4);
            cp_async16(dst, &X[(size_t)grow * FIN + kt + q]);
        }
        CP_COMMIT();
    };

    const int cg = t & 7;
    const int rg = t >> 3;

    unsigned long long acc[8][4];
#pragma unroll
    for (int i = 0; i < 8; i++)
#pragma unroll
        for (int j = 0; j < 4; j++) acc[i][j] = 0ull;

    issue_tile(0, 0);

    const int NIT = FIN / PROJ_KT;           // 12
    for (int it = 0; it < NIT; it++) {
        if (it + 1 < NIT) {
            issue_tile((it + 1) * PROJ_KT, (it + 1) & 1);
            CP_WAIT(1);
        } else {
            CP_WAIT(0);
        }
        __syncthreads();
        const float* Xb = Xs + (it & 1) * (PROJ_BR * PROJ_XS);
#pragma unroll
        for (int q = 0; q < 8; q++) {
            float4 xq[8];
#pragma unroll
            for (int i = 0; i < 8; i++)
                xq[i] = *(const float4*)&Xb[(rg + 32 * i) * PROJ_XS + q * 4];
#pragma unroll
            for (int kk = 0; kk < 4; kk++) {
                const int k = it * PROJ_KT + q * 4 + kk;
                const ulonglong2 w0 = *(const ulonglong2*)&WT[k * WT_STR + cg * 8];
                const ulonglong2 w1 = *(const ulonglong2*)&WT[k * WT_STR + cg * 8 + 4];
#pragma unroll
                for (int i = 0; i < 8; i++) {
                    unsigned long long xv =
                        bcast2(((const float*)&xq[i])[kk]);
                    acc[i][0] = ffma2(xv, w0.x, acc[i][0]);
                    acc[i][1] = ffma2(xv, w0.y, acc[i][1]);
                    acc[i][2] = ffma2(xv, w1.x, acc[i][2]);
                    acc[i][3] = ffma2(xv, w1.y, acc[i][3]);
                }
            }
        }
        __syncthreads();
    }

    float bias[8];
#pragma unroll
    for (int j = 0; j < 8; j++) bias[j] = b[cg * 8 + j];
#pragma unroll
    for (int i = 0; i < 8; i++) {
        int grow = row0 + rg + 32 * i;
        if (grow < NP) {
            float o[8];
#pragma unroll
            for (int j = 0; j < 4; j++) {
                float2 p = unpack2(acc[i][j]);
                o[2 * j]     = fmaxf(p.x + bias[2 * j], 0.f);
                o[2 * j + 1] = fmaxf(p.y + bias[2 * j + 1], 0.f);
            }
            float* dst = &g_x0[(size_t)grow * H + cg * 8];
            *(float4*)dst       = make_float4(o[0], o[1], o[2], o[3]);
            *(float4*)(dst + 4) = make_float4(o[4], o[5], o[6], o[7]);
        }
    }
}

// ---------------------------------------------------------------------------
// atomic-free aggregation (527k warps; writes mean directly)
// ---------------------------------------------------------------------------
__global__ void agg_kernel(const float* __restrict__ x) {
    int w = (blockIdx.x * blockDim.x + threadIdx.x) >> 5;
    if (w >= NTOT) return;
    const int lane = threadIdx.x & 31;
    const int half = lane >> 4;
    const int li   = lane & 15;
    const size_t co = (size_t)(li * 4);

    const int beg = g_row[w];
    const int end = g_row[w + 1];

    float4 acc = make_float4(0.f, 0.f, 0.f, 0.f);

    int j = beg + half;
    for (; j + 6 < end; j += 8) {
        int s0 = g_eidx[j];
        int s1 = g_eidx[j + 2];
        int s2 = g_eidx[j + 4];
        int s3 = g_eidx[j + 6];
        float4 v0 = *(const float4*)&x[(size_t)s0 * H + co];
        float4 v1 = *(const float4*)&x[(size_t)s1 * H + co];
        float4 v2 = *(const float4*)&x[(size_t)s2 * H + co];
        float4 v3 = *(const float4*)&x[(size_t)s3 * H + co];
        acc.x += v0.x + v1.x + v2.x + v3.x;
        acc.y += v0.y + v1.y + v2.y + v3.y;
        acc.z += v0.z + v1.z + v2.z + v3.z;
        acc.w += v0.w + v1.w + v2.w + v3.w;
    }
    for (; j < end; j += 2) {
        int s = g_eidx[j];
        float4 v = *(const float4*)&x[(size_t)s * H + co];
        acc.x += v.x; acc.y += v.y; acc.z += v.z; acc.w += v.w;
    }

    acc.x += __shfl_xor_sync(0xffffffffu, acc.x, 16);
    acc.y += __shfl_xor_sync(0xffffffffu, acc.y, 16);
    acc.z += __shfl_xor_sync(0xffffffffu, acc.z, 16);
    acc.w += __shfl_xor_sync(0xffffffffu, acc.w, 16);

    if (half == 0) {
        float iv = g_deg[w];
        acc.x *= iv; acc.y *= iv; acc.z *= iv; acc.w *= iv;
        *(float4*)&g_agg[(size_t)w * H + co] = acc;
    }
}

// ---------------------------------------------------------------------------
// SAGE combine (quad a/x loads; agg already holds the mean)
// out = [relu]( agg @ Wl^T + bl + x @ Wr^T )
// ---------------------------------------------------------------------------
#define CMB_WSTR 68
template <int OUT, bool RELU>
__global__ void combine_kernel(const float* __restrict__ agg,
                               const float* __restrict__ x,
                               const float* __restrict__ Wl,
                               const float* __restrict__ bl,
                               const float* __restrict__ Wr,
                               float* __restrict__ out) {
    constexpr int BR = 128;
    constexpr int COLG = OUT / 8;
    constexpr int RG = 256 / COLG;
    constexpr int R = BR / RG;
    constexpr int STR = 68;

    extern __shared__ float sm[];
    float* WlT = sm;
    float* WrT = WlT + 64 * CMB_WSTR;
    float* As  = WrT + 64 * CMB_WSTR;
    float* Xs  = As + BR * STR;

    const int t = threadIdx.x;
    for (int e = t; e < (OUT * 64) / 4; e += 256) {
        float4 vl = reinterpret_cast<const float4*>(Wl)[e];
        float4 vr = reinterpret_cast<const float4*>(Wr)[e];
        int flat = e * 4;
        int c = flat / 64, k = flat % 64;
        WlT[(k + 0) * CMB_WSTR + c] = vl.x;
        WlT[(k + 1) * CMB_WSTR + c] = vl.y;
        WlT[(k + 2) * CMB_WSTR + c] = vl.z;
        WlT[(k + 3) * CMB_WSTR + c] = vl.w;
        WrT[(k + 0) * CMB_WSTR + c] = vr.x;
        WrT[(k + 1) * CMB_WSTR + c] = vr.y;
        WrT[(k + 2) * CMB_WSTR + c] = vr.z;
        WrT[(k + 3) * CMB_WSTR + c] = vr.w;
    }

    const int row0 = blockIdx.x * BR;
    for (int e = t; e < BR * 16; e += 256) {
        int r = e >> 4, q = (e & 15) * 4;
        int grow = row0 + r;
        if (grow >= NTOT) grow = NTOT - 1;
        *(float4*)&As[r * STR + q] = *(const float4*)&agg[(size_t)grow * H + q];
        *(float4*)&Xs[r * STR + q] = *(const float4*)&x[(size_t)grow * H + q];
    }
    __syncthreads();

    const int cg = t % COLG;
    const int rg = t / COLG;

    unsigned long long acc[R][4];
#pragma unroll
    for (int i = 0; i < R; i++)
#pragma unroll
        for (int j = 0; j < 4; j++) acc[i][j] = 0ull;

#pragma unroll
    for (int q = 0; q < 16; q++) {           // 64 k = 16 quads
        float4 aq[R], xq[R];
#pragma unroll
        for (int i = 0; i < R; i++) {
            const int r = rg + RG * i;
            aq[i] = *(const float4*)&As[r * STR + q * 4];
            xq[i] = *(const float4*)&Xs[r * STR + q * 4];
        }
#pragma unroll
        for (int kk = 0; kk < 4; kk++) {
            const int k = q * 4 + kk;
            const ulonglong2 wl0 = *(const ulonglong2*)&WlT[k * CMB_WSTR + cg * 8];
            const ulonglong2 wl1 = *(const ulonglong2*)&WlT[k * CMB_WSTR + cg * 8 + 4];
            const ulonglong2 wr0 = *(const ulonglong2*)&WrT[k * CMB_WSTR + cg * 8];
            const ulonglong2 wr1 = *(const ulonglong2*)&WrT[k * CMB_WSTR + cg * 8 + 4];
#pragma unroll
            for (int i = 0; i < R; i++) {
                unsigned long long a2 = bcast2(((const float*)&aq[i])[kk]);
                unsigned long long x2 = bcast2(((const float*)&xq[i])[kk]);
                acc[i][0] = ffma2(a2, wl0.x, acc[i][0]);
                acc[i][0] = ffma2(x2, wr0.x, acc[i][0]);
                acc[i][1] = ffma2(a2, wl0.y, acc[i][1]);
                acc[i][1] = ffma2(x2, wr0.y, acc[i][1]);
                acc[i][2] = ffma2(a2, wl1.x, acc[i][2]);
                acc[i][2] = ffma2(x2, wr1.x, acc[i][2]);
                acc[i][3] = ffma2(a2, wl1.y, acc[i][3]);
                acc[i][3] = ffma2(x2, wr1.y, acc[i][3]);
            }
        }
    }

    float bias[8];
#pragma unroll
    for (int j = 0; j < 8; j++) bias[j] = bl[cg * 8 + j];
#pragma unroll
    for (int i = 0; i < R; i++) {
        int grow = row0 + rg + RG * i;
        if (grow < NTOT) {
            float o[8];
#pragma unroll
            for (int j = 0; j < 4; j++) {
                float2 p = unpack2(acc[i][j]);
                float v0 = p.x + bias[2 * j];
                float v1 = p.y + bias[2 * j + 1];
                if (RELU) { v0 = fmaxf(v0, 0.f); v1 = fmaxf(v1, 0.f); }
                o[2 * j] = v0; o[2 * j + 1] = v1;
            }
            float* dst = &out[(size_t)grow * OUT + cg * 8];
            *(float4*)dst       = make_float4(o[0], o[1], o[2], o[3]);
            *(float4*)(dst + 4) = make_float4(o[4], o[5], o[6], o[7]);
        }
    }
}

// ---------------------------------------------------------------------------
// Host launch sequence (graph-capturable, allocation-free).
// Fork-join overlap preserved; submission order puts proj at my launch
// index 3 so ncu -s 5 -c 1 (harness prepends 2) captures proj:
//   submit: zero(0,s2) cnt(1,s2) scan(2,s2) proj(3,main) fill(4,s2)
//           init(5,s2) join agg1 cmb1 agg2 cmb2
// ---------------------------------------------------------------------------
extern "C" void kernel_launch(void* const* d_in, const int* in_sizes, int n_in,
                              void* d_out, int out_size) {
    (void)in_sizes; (void)n_in; (void)out_size;

    const float* x_product = (const float*)d_in[0];
    const int*   pb_src    = (const int*)d_in[1];
    const int*   pb_dst    = (const int*)d_in[2];
    const int*   pc_src    = (const int*)d_in[3];
    const int*   pc_dst    = (const int*)d_in[4];
    const int*   ps_src    = (const int*)d_in[5];
    const int*   ps_dst    = (const int*)d_in[6];
    const float* W_proj    = (const float*)d_in[7];
    const float* b_proj    = (const float*)d_in[8];
    const float* emb_b     = (const float*)d_in[9];
    const float* emb_c     = (const float*)d_in[10];
    const float* emb_s     = (const float*)d_in[11];
    const float* W1l       = (const float*)d_in[12];
    const float* b1l       = (const float*)d_in[13];
    const float* W1r       = (const float*)d_in[14];
    const float* W2l       = (const float*)d_in[15];
    const float* b2l       = (const float*)d_in[16];
    const float* W2r       = (const float*)d_in[17];
    float* out = (float*)d_out;

    float *px0, *ph1, *pagg;
    cudaGetSymbolAddress((void**)&px0, g_x0);
    cudaGetSymbolAddress((void**)&ph1, g_h1);
    cudaGetSymbolAddress((void**)&pagg, g_agg);

    const int CMB_SMEM = (2 * 64 * CMB_WSTR + 2 * 128 * 68) * 4;   // 104448
    cudaFuncSetAttribute(proj_kernel,
                         cudaFuncAttributeMaxDynamicSharedMemorySize, PROJ_SMEM);
    cudaFuncSetAttribute(combine_kernel<64, true>,
                         cudaFuncAttributeMaxDynamicSharedMemorySize, CMB_SMEM);
    cudaFuncSetAttribute(combine_kernel<32, false>,
                         cudaFuncAttributeMaxDynamicSharedMemorySize, CMB_SMEM);

    const int ZRB = (NTOT + 255) / 256;
    const int CPB = ((NB + NCA + NSH) * H / 4 + 255) / 256;
    const int PRB = (NP + PROJ_BR - 1) / PROJ_BR;   // 1954
    const int CMB = (NTOT + 127) / 128;
    const int AGB = (NTOT + 7) / 8;
    const dim3 EG((EE + 255) / 256, 6);

    if (g_aux.s2) {
        cudaStream_t s2 = g_aux.s2;
        cudaEventRecord(g_aux.evFork, 0);
        cudaStreamWaitEvent(s2, g_aux.evFork, 0);
        // side chain part 1 (launch indices 0-2)
        zero_kernel<<<ZRB, 256, 0, s2>>>();
        cnt_kernel<<<EG, 256, 0, s2>>>(pb_src, pb_dst, pc_src, pc_dst, ps_src, ps_dst);
        scan_kernel<<<SCAN_NB, 1024, 0, s2>>>();
        // main: projection (launch index 3 -> profiled), concurrent with side
        proj_kernel<<<PRB, 256, PROJ_SMEM>>>(x_product, W_proj, b_proj);
        // side chain part 2 (indices 4-5; stream-ordered after scan)
        fill_kernel<<<EG, 256, 0, s2>>>(pb_src, pb_dst, pc_src, pc_dst, ps_src, ps_dst);
        init_kernel<<<CPB, 256, 0, s2>>>(emb_b, emb_c, emb_s);
        cudaEventRecord(g_aux.evJoin, s2);
        cudaStreamWaitEvent(0, g_aux.evJoin, 0);
    } else {
        zero_kernel<<<ZRB, 256>>>();
        cnt_kernel<<<EG, 256>>>(pb_src, pb_dst, pc_src, pc_dst, ps_src, ps_dst);
        scan_kernel<<<SCAN_NB, 1024>>>();
        proj_kernel<<<PRB, 256, PROJ_SMEM>>>(x_product, W_proj, b_proj);
        fill_kernel<<<EG, 256>>>(pb_src, pb_dst, pc_src, pc_dst, ps_src, ps_dst);
        init_kernel<<<CPB, 256>>>(emb_b, emb_c, emb_s);
    }

    // layers (null stream, after join)
    agg_kernel<<<AGB, 256>>>(px0);
    combine_kernel<64, true><<<CMB, 256, CMB_SMEM>>>(pagg, px0, W1l, b1l, W1r, ph1);
    agg_kernel<<<AGB, 256>>>(ph1);
    combine_kernel<32, false><<<CMB, 256, CMB_SMEM>>>(pagg, ph1, W2l, b2l, W2r, out);
}

// round 17
// speedup vs baseline: 1.3753x; 1.0059x over previous
#include <cuda_runtime.h>
#include <cstdint>

// ---------------------------------------------------------------------------
// Problem constants
// ---------------------------------------------------------------------------
#define NP   500000
#define NB   20000
#define NCA  5000
#define NSH  2000
#define NTOT 527000
#define EE   500000
#define E6   (6 * EE)
#define H    64
#define ODIM 32
#define FIN  384

#define BOFF NP
#define COFF (NP + NB)
#define SOFF (NP + NB + NCA)

#define SCAN_NB ((NTOT + 1023) / 1024)

// ---------------------------------------------------------------------------
// Scratch (device globals: allocation-free rule)
// ---------------------------------------------------------------------------
__device__ float g_x0[(size_t)NTOT * H];
__device__ float g_h1[(size_t)NTOT * H];
__device__ float g_agg[(size_t)NTOT * H];
__device__ float g_deg[NTOT];
__device__ int   g_cnt[NTOT];
__device__ int   g_row[NTOT + 1];
__device__ int   g_fill[NTOT];
__device__ int   g_eidx[E6];
__device__ unsigned long long g_look[SCAN_NB];

// ---------------------------------------------------------------------------
// Side stream + events for fork-join overlap (created at binary load).
// Falls back to fully serial null-stream execution if creation fails.
// ---------------------------------------------------------------------------
struct AuxStreams {
    cudaStream_t s2 = nullptr;
    cudaEvent_t  evFork = nullptr, evJoin = nullptr;
    AuxStreams() {
        if (cudaStreamCreateWithFlags(&s2, cudaStreamNonBlocking) != cudaSuccess)
            s2 = nullptr;
        if (s2) {
            if (cudaEventCreateWithFlags(&evFork, cudaEventDisableTiming) != cudaSuccess ||
                cudaEventCreateWithFlags(&evJoin, cudaEventDisableTiming) != cudaSuccess) {
                s2 = nullptr;
            }
        }
    }
};
static AuxStreams g_aux;

// ---------------------------------------------------------------------------
// f32x2 packed-FMA + cp.async helpers
// ---------------------------------------------------------------------------
__device__ __forceinline__ unsigned long long ffma2(unsigned long long a,
                                                    unsigned long long b,
                                                    unsigned long long c) {
    unsigned long long d;
    asm("fma.rn.f32x2 %0, %1, %2, %3;" : "=l"(d) : "l"(a), "l"(b), "l"(c));
    return d;
}
__device__ __forceinline__ unsigned long long bcast2(float v) {
    unsigned long long r;
    unsigned int u = __float_as_uint(v);
    asm("mov.b64 %0, {%1, %2};" : "=l"(r) : "r"(u), "r"(u));
    return r;
}
__device__ __forceinline__ float2 unpack2(unsigned long long v) {
    unsigned int lo, hi;
    asm("mov.b64 {%0, %1}, %2;" : "=r"(lo), "=r"(hi) : "l"(v));
    return make_float2(__uint_as_float(lo), __uint_as_float(hi));
}
__device__ __forceinline__ void cp_async16(unsigned int smem_dst, const void* gsrc) {
    asm volatile("cp.async.cg.shared.global [%0], [%1], 16;\n"
                 :: "r"(smem_dst), "l"(gsrc));
}
#define CP_COMMIT()  asm volatile("cp.async.commit_group;\n" ::: "memory")
#define CP_WAIT(n)   asm volatile("cp.async.wait_group %0;\n" :: "n"(n) : "memory")

// ---------------------------------------------------------------------------
// zero counts + lookback words
// ---------------------------------------------------------------------------
__global__ void zero_kernel() {
    int i = blockIdx.x * 256 + threadIdx.x;
    if (i < NTOT) g_cnt[i] = 0;
    if (i < SCAN_NB) g_look[i] = 0ull;
}

// ---------------------------------------------------------------------------
// in-degree counts. blockIdx.y = relation id (0..5).
// ---------------------------------------------------------------------------
__global__ void cnt_kernel(const int* __restrict__ pbs, const int* __restrict__ pbd,
                           const int* __restrict__ pcs, const int* __restrict__ pcd,
                           const int* __restrict__ pss, const int* __restrict__ psd) {
    int i = blockIdx.x * 256 + threadIdx.x;
    if (i >= EE) return;
    int d;
    switch (blockIdx.y) {
        case 0:  d = pbd[i] + BOFF; break;
        case 1:  d = pbs[i];        break;
        case 2:  d = pcd[i] + COFF; break;
        case 3:  d = pcs[i];        break;
        case 4:  d = psd[i] + SOFF; break;
        default: d = pss[i];        break;
    }
    atomicAdd(&g_cnt[d], 1);
}

// ---------------------------------------------------------------------------
// decoupled-lookback exclusive scan (row starts, fill cursors, 1/deg)
// ---------------------------------------------------------------------------
__global__ void scan_kernel() {
    __shared__ int sb[1024];
    __shared__ int s_base;
    const int t = threadIdx.x;
    const int bid = blockIdx.x;
    const int i = bid * 1024 + t;

    int c = (i < NTOT) ? g_cnt[i] : 0;
    sb[t] = c;
    __syncthreads();
    for (int off = 1; off < 1024; off <<= 1) {
        int u = (t >= off) ? sb[t - off] : 0;
        __syncthreads();
        sb[t] += u;
        __syncthreads();
    }
    const int incl = sb[t];
    const int aggregate = sb[1023];

    if (t == 0) {
        unsigned long long st = (bid == 0) ? 2ull : 1ull;
        atomicExch(&g_look[bid], (st << 32) | (unsigned int)aggregate);
    }

    if (bid == 0) {
        if (t == 0) s_base = 0;
    } else if (t < 32) {
        int acc = 0;
        int windowEnd = bid - 1;
        while (true) {
            int p = windowEnd - t;
            unsigned long long w = 0;
            if (p >= 0) w = atomicAdd(&g_look[p], 0ull);
            unsigned int st  = (p >= 0) ? (unsigned int)(w >> 32) : 2u;
            int val          = (p >= 0) ? (int)(unsigned int)w : 0;
            unsigned int ready = __ballot_sync(0xffffffffu, st != 0u);
            if (ready != 0xffffffffu) continue;
            unsigned int haveIncl = __ballot_sync(0xffffffffu, st == 2u);
            if (haveIncl) {
                int L = __ffs(haveIncl) - 1;
                int contrib = (t <= L) ? val : 0;
#pragma unroll
                for (int o = 16; o; o >>= 1)
                    contrib += __shfl_xor_sync(0xffffffffu, contrib, o);
                acc += contrib;
                break;
            } else {
                int contrib = val;
#pragma unroll
                for (int o = 16; o; o >>= 1)
                    contrib += __shfl_xor_sync(0xffffffffu, contrib, o);
                acc += contrib;
                windowEnd -= 32;
            }
        }
        if (t == 0) {
            s_base = acc;
            atomicExch(&g_look[bid],
                       (2ull << 32) | (unsigned int)(acc + aggregate));
        }
    }
    __syncthreads();
    const int base = s_base;

    if (i < NTOT) {
        int excl = base + incl - c;
        g_row[i]  = excl;
        g_fill[i] = excl;
        g_deg[i]  = 1.0f / fmaxf((float)c, 1.0f);
    }
    if (i == NTOT - 1) g_row[NTOT] = E6;
}

// ---------------------------------------------------------------------------
// fill adjacency
// ---------------------------------------------------------------------------
__global__ void fill_kernel(const int* __restrict__ pbs, const int* __restrict__ pbd,
                            const int* __restrict__ pcs, const int* __restrict__ pcd,
                            const int* __restrict__ pss, const int* __restrict__ psd) {
    int i = blockIdx.x * 256 + threadIdx.x;
    if (i >= EE) return;
    int s, d;
    switch (blockIdx.y) {
        case 0:  s = pbs[i];        d = pbd[i] + BOFF; break;
        case 1:  s = pbd[i] + BOFF; d = pbs[i];        break;
        case 2:  s = pcs[i];        d = pcd[i] + COFF; break;
        case 3:  s = pcd[i] + COFF; d = pcs[i];        break;
        case 4:  s = pss[i];        d = psd[i] + SOFF; break;
        default: s = psd[i] + SOFF; d = pss[i];        break;
    }
    int pos = atomicAdd(&g_fill[d], 1);
    g_eidx[pos] = s;
}

// ---------------------------------------------------------------------------
// copy embeddings into g_x0 rows [NP, NTOT)
// ---------------------------------------------------------------------------
__global__ void init_kernel(const float* __restrict__ eb,
                            const float* __restrict__ ec,
                            const float* __restrict__ es) {
    int i = blockIdx.x * 256 + threadIdx.x;
    const int nb4 = NB * H / 4, nc4 = NCA * H / 4, ns4 = NSH * H / 4;
    if (i < nb4 + nc4 + ns4) {
        float4* dst = reinterpret_cast<float4*>(g_x0 + (size_t)NP * H);
        float4 v;
        if (i < nb4)              v = reinterpret_cast<const float4*>(eb)[i];
        else if (i < nb4 + nc4)   v = reinterpret_cast<const float4*>(ec)[i - nb4];
        else                      v = reinterpret_cast<const float4*>(es)[i - nb4 - nc4];
        dst[i] = v;
    }
}

// ---------------------------------------------------------------------------
// projection v8: v7 tile shape (KT=32, 128B lines) with TRIPLE buffer and
// ONE barrier per tile (was 2). The single barrier both releases the
// computed buffer (it-1)%3 for refill and rendezvous-es the resident tile;
// tiles it+1, it+2 stay in flight during compute (2x memory depth).
// g_x0[0:NP] = relu(x_product @ W_proj^T + b_proj)
// 256 threads, 256 rows/block, 8 rows x 8 cols per thread, FFMA2.
// ---------------------------------------------------------------------------
#define PROJ_BR 256
#define PROJ_KT 32
#define PROJ_XS 36
#define WT_STR  68
#define PROJ_NBUF 3
#define PROJ_SMEM ((FIN * WT_STR + PROJ_NBUF * PROJ_BR * PROJ_XS) * 4) // 215040

__global__ void __launch_bounds__(256, 1)
proj_kernel(const float* __restrict__ X,
            const float* __restrict__ W,
            const float* __restrict__ b) {
    extern __shared__ float sm[];
    float* WT = sm;                          // [384][68] k-major, padded
    float* Xs = sm + FIN * WT_STR;           // [3][256][PROJ_XS]
    const int t = threadIdx.x;
    const int row0 = blockIdx.x * PROJ_BR;

    const unsigned int xs_smem =
        (unsigned int)__cvta_generic_to_shared(Xs);

    for (int e = t; e < (FIN * 64) / 4; e += 256) {
        float4 v = reinterpret_cast<const float4*>(W)[e];
        int flat = e * 4;
        int c = flat / FIN, k = flat % FIN;
        WT[(k + 0) * WT_STR + c] = v.x;
        WT[(k + 1) * WT_STR + c] = v.y;
        WT[(k + 2) * WT_STR + c] = v.z;
        WT[(k + 3) * WT_STR + c] = v.w;
    }

    // one 32-k (128 B/row) tile of X into buffer buf
    auto issue_tile = [&](int kt, int buf) {
#pragma unroll
        for (int e = t; e < PROJ_BR * 8; e += 256) {
            int r = e >> 3, q = (e & 7) * 4;
            int grow = row0 + r;
            if (grow >= NP) grow = NP - 1;
            unsigned int dst = xs_smem +
                (unsigned int)((buf * PROJ_BR * PROJ_XS + r * PROJ_XS + q) * 4);
            cp_async16(dst, &X[(size_t)grow * FIN + kt + q]);
        }
        CP_COMMIT();
    };

    const int cg = t & 7;
    const int rg = t >> 3;

    unsigned long long acc[8][4];
#pragma unroll
    for (int i = 0; i < 8; i++)
#pragma unroll
        for (int j = 0; j < 4; j++) acc[i][j] = 0ull;

    issue_tile(0, 0);
    issue_tile(PROJ_KT, 1);

    const int NIT = FIN / PROJ_KT;           // 12
    for (int it = 0; it < NIT; it++) {
        if (it < NIT - 1) { CP_WAIT(1); }    // tile it resident
        else             { CP_WAIT(0); }
        __syncthreads();                     // + buffer (it+2)%3 now free
        if (it + 2 < NIT)
            issue_tile((it + 2) * PROJ_KT, (it + 2) % PROJ_NBUF);

        const float* Xb = Xs + (it % PROJ_NBUF) * (PROJ_BR * PROJ_XS);
#pragma unroll
        for (int q = 0; q < 8; q++) {
            float4 xq[8];
#pragma unroll
            for (int i = 0; i < 8; i++)
                xq[i] = *(const float4*)&Xb[(rg + 32 * i) * PROJ_XS + q * 4];
#pragma unroll
            for (int kk = 0; kk < 4; kk++) {
                const int k = it * PROJ_KT + q * 4 + kk;
                const ulonglong2 w0 = *(const ulonglong2*)&WT[k * WT_STR + cg * 8];
                const ulonglong2 w1 = *(const ulonglong2*)&WT[k * WT_STR + cg * 8 + 4];
#pragma unroll
                for (int i = 0; i < 8; i++) {
                    unsigned long long xv =
                        bcast2(((const float*)&xq[i])[kk]);
                    acc[i][0] = ffma2(xv, w0.x, acc[i][0]);
                    acc[i][1] = ffma2(xv, w0.y, acc[i][1]);
                    acc[i][2] = ffma2(xv, w1.x, acc[i][2]);
                    acc[i][3] = ffma2(xv, w1.y, acc[i][3]);
                }
            }
        }
        // no trailing barrier: next iteration's barrier covers reuse
    }

    float bias[8];
#pragma unroll
    for (int j = 0; j < 8; j++) bias[j] = b[cg * 8 + j];
#pragma unroll
    for (int i = 0; i < 8; i++) {
        int grow = row0 + rg + 32 * i;
        if (grow < NP) {
            float o[8];
#pragma unroll
            for (int j = 0; j < 4; j++) {
                float2 p = unpack2(acc[i][j]);
                o[2 * j]     = fmaxf(p.x + bias[2 * j], 0.f);
                o[2 * j + 1] = fmaxf(p.y + bias[2 * j + 1], 0.f);
            }
            float* dst = &g_x0[(size_t)grow * H + cg * 8];
            *(float4*)dst       = make_float4(o[0], o[1], o[2], o[3]);
            *(float4*)(dst + 4) = make_float4(o[4], o[5], o[6], o[7]);
        }
    }
}

// ---------------------------------------------------------------------------
// atomic-free aggregation (527k warps; writes mean directly)
// ---------------------------------------------------------------------------
__global__ void agg_kernel(const float* __restrict__ x) {
    int w = (blockIdx.x * blockDim.x + threadIdx.x) >> 5;
    if (w >= NTOT) return;
    const int lane = threadIdx.x & 31;
    const int half = lane >> 4;
    const int li   = lane & 15;
    const size_t co = (size_t)(li * 4);

    const int beg = g_row[w];
    const int end = g_row[w + 1];

    float4 acc = make_float4(0.f, 0.f, 0.f, 0.f);

    int j = beg + half;
    for (; j + 6 < end; j += 8) {
        int s0 = g_eidx[j];
        int s1 = g_eidx[j + 2];
        int s2 = g_eidx[j + 4];
        int s3 = g_eidx[j + 6];
        float4 v0 = *(const float4*)&x[(size_t)s0 * H + co];
        float4 v1 = *(const float4*)&x[(size_t)s1 * H + co];
        float4 v2 = *(const float4*)&x[(size_t)s2 * H + co];
        float4 v3 = *(const float4*)&x[(size_t)s3 * H + co];
        acc.x += v0.x + v1.x + v2.x + v3.x;
        acc.y += v0.y + v1.y + v2.y + v3.y;
        acc.z += v0.z + v1.z + v2.z + v3.z;
        acc.w += v0.w + v1.w + v2.w + v3.w;
    }
    for (; j < end; j += 2) {
        int s = g_eidx[j];
        float4 v = *(const float4*)&x[(size_t)s * H + co];
        acc.x += v.x; acc.y += v.y; acc.z += v.z; acc.w += v.w;
    }

    acc.x += __shfl_xor_sync(0xffffffffu, acc.x, 16);
    acc.y += __shfl_xor_sync(0xffffffffu, acc.y, 16);
    acc.z += __shfl_xor_sync(0xffffffffu, acc.z, 16);
    acc.w += __shfl_xor_sync(0xffffffffu, acc.w, 16);

    if (half == 0) {
        float iv = g_deg[w];
        acc.x *= iv; acc.y *= iv; acc.z *= iv; acc.w *= iv;
        *(float4*)&g_agg[(size_t)w * H + co] = acc;
    }
}

// ---------------------------------------------------------------------------
// SAGE combine (quad a/x loads; agg already holds the mean)
// out = [relu]( agg @ Wl^T + bl + x @ Wr^T )
// ---------------------------------------------------------------------------
#define CMB_WSTR 68
template <int OUT, bool RELU>
__global__ void combine_kernel(const float* __restrict__ agg,
                               const float* __restrict__ x,
                               const float* __restrict__ Wl,
                               const float* __restrict__ bl,
                               const float* __restrict__ Wr,
                               float* __restrict__ out) {
    constexpr int BR = 128;
    constexpr int COLG = OUT / 8;
    constexpr int RG = 256 / COLG;
    constexpr int R = BR / RG;
    constexpr int STR = 68;

    extern __shared__ float sm[];
    float* WlT = sm;
    float* WrT = WlT + 64 * CMB_WSTR;
    float* As  = WrT + 64 * CMB_WSTR;
    float* Xs  = As + BR * STR;

    const int t = threadIdx.x;
    for (int e = t; e < (OUT * 64) / 4; e += 256) {
        float4 vl = reinterpret_cast<const float4*>(Wl)[e];
        float4 vr = reinterpret_cast<const float4*>(Wr)[e];
        int flat = e * 4;
        int c = flat / 64, k = flat % 64;
        WlT[(k + 0) * CMB_WSTR + c] = vl.x;
        WlT[(k + 1) * CMB_WSTR + c] = vl.y;
        WlT[(k + 2) * CMB_WSTR + c] = vl.z;
        WlT[(k + 3) * CMB_WSTR + c] = vl.w;
        WrT[(k + 0) * CMB_WSTR + c] = vr.x;
        WrT[(k + 1) * CMB_WSTR + c] = vr.y;
        WrT[(k + 2) * CMB_WSTR + c] = vr.z;
        WrT[(k + 3) * CMB_WSTR + c] = vr.w;
    }

    const int row0 = blockIdx.x * BR;
    for (int e = t; e < BR * 16; e += 256) {
        int r = e >> 4, q = (e & 15) * 4;
        int grow = row0 + r;
        if (grow >= NTOT) grow = NTOT - 1;
        *(float4*)&As[r * STR + q] = *(const float4*)&agg[(size_t)grow * H + q];
        *(float4*)&Xs[r * STR + q] = *(const float4*)&x[(size_t)grow * H + q];
    }
    __syncthreads();

    const int cg = t % COLG;
    const int rg = t / COLG;

    unsigned long long acc[R][4];
#pragma unroll
    for (int i = 0; i < R; i++)
#pragma unroll
        for (int j = 0; j < 4; j++) acc[i][j] = 0ull;

#pragma unroll
    for (int q = 0; q < 16; q++) {           // 64 k = 16 quads
        float4 aq[R], xq[R];
#pragma unroll
        for (int i = 0; i < R; i++) {
            const int r = rg + RG * i;
            aq[i] = *(const float4*)&As[r * STR + q * 4];
            xq[i] = *(const float4*)&Xs[r * STR + q * 4];
        }
#pragma unroll
        for (int kk = 0; kk < 4; kk++) {
            const int k = q * 4 + kk;
            const ulonglong2 wl0 = *(const ulonglong2*)&WlT[k * CMB_WSTR + cg * 8];
            const ulonglong2 wl1 = *(const ulonglong2*)&WlT[k * CMB_WSTR + cg * 8 + 4];
            const ulonglong2 wr0 = *(const ulonglong2*)&WrT[k * CMB_WSTR + cg * 8];
            const ulonglong2 wr1 = *(const ulonglong2*)&WrT[k * CMB_WSTR + cg * 8 + 4];
#pragma unroll
            for (int i = 0; i < R; i++) {
                unsigned long long a2 = bcast2(((const float*)&aq[i])[kk]);
                unsigned long long x2 = bcast2(((const float*)&xq[i])[kk]);
                acc[i][0] = ffma2(a2, wl0.x, acc[i][0]);
                acc[i][0] = ffma2(x2, wr0.x, acc[i][0]);
                acc[i][1] = ffma2(a2, wl0.y, acc[i][1]);
                acc[i][1] = ffma2(x2, wr0.y, acc[i][1]);
                acc[i][2] = ffma2(a2, wl1.x, acc[i][2]);
                acc[i][2] = ffma2(x2, wr1.x, acc[i][2]);
                acc[i][3] = ffma2(a2, wl1.y, acc[i][3]);
                acc[i][3] = ffma2(x2, wr1.y, acc[i][3]);
            }
        }
    }

    float bias[8];
#pragma unroll
    for (int j = 0; j < 8; j++) bias[j] = bl[cg * 8 + j];
#pragma unroll
    for (int i = 0; i < R; i++) {
        int grow = row0 + rg + RG * i;
        if (grow < NTOT) {
            float o[8];
#pragma unroll
            for (int j = 0; j < 4; j++) {
                float2 p = unpack2(acc[i][j]);
                float v0 = p.x + bias[2 * j];
                float v1 = p.y + bias[2 * j + 1];
                if (RELU) { v0 = fmaxf(v0, 0.f); v1 = fmaxf(v1, 0.f); }
                o[2 * j] = v0; o[2 * j + 1] = v1;
            }
            float* dst = &out[(size_t)grow * OUT + cg * 8];
            *(float4*)dst       = make_float4(o[0], o[1], o[2], o[3]);
            *(float4*)(dst + 4) = make_float4(o[4], o[5], o[6], o[7]);
        }
    }
}

// ---------------------------------------------------------------------------
// Host launch sequence (graph-capturable, allocation-free).
// Fork-join overlap; proj is my launch index 3 (harness prepends 2;
// ncu -s 5 -c 1 captures proj).
// ---------------------------------------------------------------------------
extern "C" void kernel_launch(void* const* d_in, const int* in_sizes, int n_in,
                              void* d_out, int out_size) {
    (void)in_sizes; (void)n_in; (void)out_size;

    const float* x_product = (const float*)d_in[0];
    const int*   pb_src    = (const int*)d_in[1];
    const int*   pb_dst    = (const int*)d_in[2];
    const int*   pc_src    = (const int*)d_in[3];
    const int*   pc_dst    = (const int*)d_in[4];
    const int*   ps_src    = (const int*)d_in[5];
    const int*   ps_dst    = (const int*)d_in[6];
    const float* W_proj    = (const float*)d_in[7];
    const float* b_proj    = (const float*)d_in[8];
    const float* emb_b     = (const float*)d_in[9];
    const float* emb_c     = (const float*)d_in[10];
    const float* emb_s     = (const float*)d_in[11];
    const float* W1l       = (const float*)d_in[12];
    const float* b1l       = (const float*)d_in[13];
    const float* W1r       = (const float*)d_in[14];
    const float* W2l       = (const float*)d_in[15];
    const float* b2l       = (const float*)d_in[16];
    const float* W2r       = (const float*)d_in[17];
    float* out = (float*)d_out;

    float *px0, *ph1, *pagg;
    cudaGetSymbolAddress((void**)&px0, g_x0);
    cudaGetSymbolAddress((void**)&ph1, g_h1);
    cudaGetSymbolAddress((void**)&pagg, g_agg);

    const int CMB_SMEM = (2 * 64 * CMB_WSTR + 2 * 128 * 68) * 4;   // 104448
    cudaFuncSetAttribute(proj_kernel,
                         cudaFuncAttributeMaxDynamicSharedMemorySize, PROJ_SMEM);
    cudaFuncSetAttribute(combine_kernel<64, true>,
                         cudaFuncAttributeMaxDynamicSharedMemorySize, CMB_SMEM);
    cudaFuncSetAttribute(combine_kernel<32, false>,
                         cudaFuncAttributeMaxDynamicSharedMemorySize, CMB_SMEM);

    const int ZRB = (NTOT + 255) / 256;
    const int CPB = ((NB + NCA + NSH) * H / 4 + 255) / 256;
    const int PRB = (NP + PROJ_BR - 1) / PROJ_BR;   // 1954
    const int CMB = (NTOT + 127) / 128;
    const int AGB = (NTOT + 7) / 8;
    const dim3 EG((EE + 255) / 256, 6);

    if (g_aux.s2) {
        cudaStream_t s2 = g_aux.s2;
        cudaEventRecord(g_aux.evFork, 0);
        cudaStreamWaitEvent(s2, g_aux.evFork, 0);
        zero_kernel<<<ZRB, 256, 0, s2>>>();
        cnt_kernel<<<EG, 256, 0, s2>>>(pb_src, pb_dst, pc_src, pc_dst, ps_src, ps_dst);
        scan_kernel<<<SCAN_NB, 1024, 0, s2>>>();
        proj_kernel<<<PRB, 256, PROJ_SMEM>>>(x_product, W_proj, b_proj);
        fill_kernel<<<EG, 256, 0, s2>>>(pb_src, pb_dst, pc_src, pc_dst, ps_src, ps_dst);
        init_kernel<<<CPB, 256, 0, s2>>>(emb_b, emb_c, emb_s);
        cudaEventRecord(g_aux.evJoin, s2);
        cudaStreamWaitEvent(0, g_aux.evJoin, 0);
    } else {
        zero_kernel<<<ZRB, 256>>>();
        cnt_kernel<<<EG, 256>>>(pb_src, pb_dst, pc_src, pc_dst, ps_src, ps_dst);
        scan_kernel<<<SCAN_NB, 1024>>>();
        proj_kernel<<<PRB, 256, PROJ_SMEM>>>(x_product, W_proj, b_proj);
        fill_kernel<<<EG, 256>>>(pb_src, pb_dst, pc_src, pc_dst, ps_src, ps_dst);
        init_kernel<<<CPB, 256>>>(emb_b, emb_c, emb_s);
    }

    // layers (null stream, after join)
    agg_kernel<<<AGB, 256>>>(px0);
    combine_kernel<64, true><<<CMB, 256, CMB_SMEM>>>(pagg, px0, W1l, b1l, W1r, ph1);
    agg_kernel<<<AGB, 256>>>(ph1);
    combine_kernel<32, false><<<CMB, 256, CMB_SMEM>>>(pagg, ph1, W2l, b2l, W2r, out);
}